// round 8
// baseline (speedup 1.0000x reference)
#include <cuda_runtime.h>

#define BATCH 4
#define NPTS  4096
#define KNB   20
#define EPSV  1e-5f
#define SLOPE 0.2f

#define PTS 16              // points per block (main kernel)
#define EDG (PTS * KNB)     // 320 edges per block
#define THR 256

#define QPB 8               // queries (= warps) per knn block
#define BCAP 128            // per-warp pass-2 buffer capacity

// scratch (device globals; no allocations allowed)
__device__ float g_wp[384 * 64];          // reindexed + s1-folded w1: Wp[m*6+c][o]
__device__ float g_w0f[384];              // s0-folded w0
__device__ int   g_idx[BATCH * NPTS * KNB];

__device__ __forceinline__ float lrelu(float v) { return fmaxf(v, SLOPE * v); }

__device__ __forceinline__ float2 ffma2(float2 a, float2 b, float2 c) {
    float2 d;
    asm("fma.rn.f32x2 %0, %1, %2, %3;"
        : "=l"(reinterpret_cast<unsigned long long&>(d))
        : "l"(reinterpret_cast<unsigned long long&>(a)),
          "l"(reinterpret_cast<unsigned long long&>(b)),
          "l"(reinterpret_cast<unsigned long long&>(c)));
    return d;
}
__device__ __forceinline__ float2 fmul2(float2 a, float2 b) {
    float2 d;
    asm("mul.rn.f32x2 %0, %1, %2;"
        : "=l"(reinterpret_cast<unsigned long long&>(d))
        : "l"(reinterpret_cast<unsigned long long&>(a)),
          "l"(reinterpret_cast<unsigned long long&>(b)));
    return d;
}

// monotone float -> uint key (total order, incl. negatives)
__device__ __forceinline__ unsigned fkey(float d) {
    unsigned b = __float_as_uint(d);
    return b ^ ((unsigned)((int)b >> 31) | 0x80000000u);
}

// ---------------------------------------------------------------------------
// KNN: warp per query, exact threshold-filter select + fused weight prep.
// Grid (NPTS/QPB, BATCH) = (512, 4), 256 threads (8 warps), 2 blocks/SM.
// d = ||p||^2 - 2 q.p (constant ||q||^2 shift preserves reference's
// -||q-p||^2 top_k ordering; self point minimal, included).
// Phase 1 (branchless): per-lane running min over its disjoint 128-candidate
//   strided subset. Phase T: T = 20th smallest of the 32 lane mins (with
//   multiplicity). The 20 smallest lane-mins are >=20 distinct elements with
//   d <= T, so the global 20th smallest <= T and every top-20 element passes
//   the filter d <= T. Phase 2: ballot-compact all passers (packed key,idx)
//   into a small smem buffer (expected ~30). Phase 3: exact top-20 by 20
//   warp-min rounds (ties -> lowest index, matching top_k). Output order is
//   irrelevant downstream (max over k). nb > BCAP -> exact full fallback.
// ---------------------------------------------------------------------------
__global__ void __launch_bounds__(256, 2) knn_prep_kernel(
    const float* __restrict__ x,
    const float* __restrict__ w0, const float* __restrict__ g0,
    const float* __restrict__ w1, const float* __restrict__ g1)
{
    extern __shared__ char dsm[];
    float4*             pts = reinterpret_cast<float4*>(dsm);                 // 65536
    unsigned long long* buf = reinterpret_cast<unsigned long long*>(dsm + 65536); // 8192

    const int tid  = threadIdx.x;
    const int lane = tid & 31;
    const int w    = tid >> 5;
    const int b    = blockIdx.y;
    const int q    = blockIdx.x * QPB + w;
    const float* xb = x + b * 3 * NPTS;

    // ---- prep: distributed over the 2048 blocks ----
    {
        const int gt = (blockIdx.y * gridDim.x + blockIdx.x) * 256 + tid;
        const float inv = rsqrtf(1.f + EPSV);
        if (gt < 384) g_w0f[gt] = w0[gt] * g0[gt / 6] * inv;
        if (gt < 384 * 64) {
            int o  = gt & 63;
            int kc = gt >> 6;
            int m  = kc / 6;
            int c  = kc - m * 6;
            g_wp[gt] = g1[o] * inv * w1[(o * 6 + c) * 64 + m];
        }
    }

    // ---- stage batch points (x,y,z,||p||^2) ----
    for (int i = tid; i < NPTS; i += 256) {
        float vx = xb[i], vy = xb[NPTS + i], vz = xb[2 * NPTS + i];
        pts[i] = make_float4(vx, vy, vz, fmaf(vx, vx, fmaf(vy, vy, vz * vz)));
    }
    __syncthreads();

    const float4 qp = pts[q];
    const float qx = qp.x, qy = qp.y, qz = qp.z;
    const float INF = __int_as_float(0x7f800000);

    // ---- phase 1: branchless per-lane min (4 independent chains) ----
    float m0 = INF, m1 = INF, m2 = INF, m3 = INF;
#pragma unroll 2
    for (int t = 0; t < NPTS / 32; t += 4) {
        float4 p0 = pts[((t + 0) << 5) + lane];
        float4 p1 = pts[((t + 1) << 5) + lane];
        float4 p2 = pts[((t + 2) << 5) + lane];
        float4 p3 = pts[((t + 3) << 5) + lane];
        m0 = fminf(m0, fmaf(-2.f, fmaf(qx, p0.x, fmaf(qy, p0.y, qz * p0.z)), p0.w));
        m1 = fminf(m1, fmaf(-2.f, fmaf(qx, p1.x, fmaf(qy, p1.y, qz * p1.z)), p1.w));
        m2 = fminf(m2, fmaf(-2.f, fmaf(qx, p2.x, fmaf(qy, p2.y, qz * p2.z)), p2.w));
        m3 = fminf(m3, fmaf(-2.f, fmaf(qx, p3.x, fmaf(qy, p3.y, qz * p3.z)), p3.w));
    }
    float val = fminf(fminf(m0, m1), fminf(m2, m3));

    // ---- threshold: T = 20th smallest lane-min (with multiplicity) ----
    float T = INF;
    for (int r = 0; r < KNB; r++) {
        float wmin = val;
#pragma unroll
        for (int d = 16; d; d >>= 1)
            wmin = fminf(wmin, __shfl_xor_sync(0xffffffffu, wmin, d));
        unsigned msk = __ballot_sync(0xffffffffu, val == wmin);
        if (lane == (__ffs(msk) - 1)) val = INF;
        T = wmin;
    }

    // ---- phase 2: compact all candidates with d <= T (same FMA expr) ----
    unsigned long long* myb = buf + w * BCAP;
    unsigned nb = 0;
    for (int t = 0; t < NPTS / 32; t++) {
        const int j = (t << 5) + lane;
        float4 p  = pts[j];
        float d   = fmaf(-2.f, fmaf(qx, p.x, fmaf(qy, p.y, qz * p.z)), p.w);
        bool pass = (d <= T);
        unsigned mask = __ballot_sync(0xffffffffu, pass);
        if (mask) {
            if (pass) {
                unsigned pos = nb + __popc(mask & ((1u << lane) - 1u));
                if (pos < BCAP)
                    myb[pos] = ((unsigned long long)fkey(d) << 32) | (unsigned)j;
            }
            nb += __popc(mask);
        }
    }
    __syncwarp();

    // ---- phase 3: exact top-20 from buffer (nb >= 20 guaranteed) ----
    int* obase = g_idx + (b * NPTS + q) * KNB;
    if (nb <= BCAP) {
        unsigned long long v[BCAP / 32];
#pragma unroll
        for (int u = 0; u < BCAP / 32; u++) {
            int t = lane + u * 32;
            v[u] = (t < (int)nb) ? myb[t] : 0xffffffffffffffffull;
        }
        for (int r = 0; r < KNB; r++) {
            unsigned long long lmin = v[0]; int lpos = 0;
#pragma unroll
            for (int u = 1; u < BCAP / 32; u++)
                if (v[u] < lmin) { lmin = v[u]; lpos = u; }
            unsigned long long wmin = lmin;
#pragma unroll
            for (int d = 16; d; d >>= 1) {
                unsigned long long o = __shfl_xor_sync(0xffffffffu, wmin, d);
                wmin = (o < wmin) ? o : wmin;
            }
            if (lmin == wmin) {
#pragma unroll
                for (int u = 0; u < BCAP / 32; u++)
                    if (u == lpos) v[u] = 0xffffffffffffffffull;
            }
            if (lane == 0) obase[r] = (int)(unsigned)(wmin & 0xffffffffull);
        }
    } else {
        // pathological fallback: exact repeated warp-min over all candidates
        unsigned long long last = 0;
        for (int r = 0; r < KNB; r++) {
            unsigned long long best = 0xffffffffffffffffull;
            for (int t = 0; t < NPTS / 32; t++) {
                const int j = (t << 5) + lane;
                float4 p  = pts[j];
                float d   = fmaf(-2.f, fmaf(qx, p.x, fmaf(qy, p.y, qz * p.z)), p.w);
                unsigned long long kk =
                    ((unsigned long long)fkey(d) << 32) | (unsigned)j;
                if (kk > last && kk < best) best = kk;
            }
#pragma unroll
            for (int d = 16; d; d >>= 1) {
                unsigned long long o = __shfl_xor_sync(0xffffffffu, best, d);
                best = (o < best) ? o : best;
            }
            if (lane == 0) obase[r] = (int)(unsigned)(best & 0xffffffffull);
            last = best;
        }
    }
}

// ---------------------------------------------------------------------------
// Fused main kernel (unchanged, 330us @ fma 70.8%): feat gather -> y1 ->
// packed f32x2 GEMM (E x 384)@(384 x 64) -> BN+LReLU -> max k -> 64->3 conv.
// ---------------------------------------------------------------------------
__global__ void __launch_bounds__(THR, 1) main_kernel(
    const float* __restrict__ x,    const float* __restrict__ b0,
    const float* __restrict__ b1,   const float* __restrict__ w_out,
    const float* __restrict__ g_out, const float* __restrict__ b_out,
    float* __restrict__ out)
{
    extern __shared__ float smem[];
    float* Wp  = smem;                 // 24576  Wp[kc][64]
    float* y1s = smem + 24576;         // 20480  y1s[m][320]
    float* fts = y1s + 20480;          //  1920  fts[c][320]
    float* x1s = fts + 1920;           //  1024  x1s[pt][64]
    float* w0f = x1s + 1024;           //   384
    float* b0s = w0f + 384;            //    64
    float* b1s = b0s + 64;             //    64

    const int tid = threadIdx.x;
    const int b   = blockIdx.x >> 8;
    const int p0  = (blockIdx.x & 255) * PTS;
    const float* xb = x + b * 3 * NPTS;

    for (int e = tid; e < EDG; e += THR) {
        int p  = e / KNB;
        int kk = e - p * KNB;
        int n  = p0 + p;
        int j  = g_idx[(b * NPTS + n) * KNB + kk];
        float xi0 = xb[n],          xi1 = xb[NPTS + n],  xi2 = xb[2 * NPTS + n];
        float xj0 = xb[j],          xj1 = xb[NPTS + j],  xj2 = xb[2 * NPTS + j];
        fts[0 * EDG + e] = xj0 - xi0;
        fts[1 * EDG + e] = xj1 - xi1;
        fts[2 * EDG + e] = xj2 - xi2;
        fts[3 * EDG + e] = xi0;
        fts[4 * EDG + e] = xi1;
        fts[5 * EDG + e] = xi2;
    }

    {
        const float4* src = reinterpret_cast<const float4*>(g_wp);
        float4* dst = reinterpret_cast<float4*>(Wp);
#pragma unroll
        for (int i = 0; i < 24; i++) dst[tid + i * THR] = src[tid + i * THR];
    }
    for (int i = tid; i < 384; i += THR) w0f[i] = g_w0f[i];
    if (tid < 64) { b0s[tid] = b0[tid]; b1s[tid] = b1[tid]; }
    __syncthreads();

    for (int i = tid; i < 64 * EDG; i += THR) {
        int m = i / EDG;
        int e = i - m * EDG;
        const float* wr = w0f + m * 6;
        float v = b0s[m];
        v = fmaf(wr[0], fts[e],           v);
        v = fmaf(wr[1], fts[EDG + e],     v);
        v = fmaf(wr[2], fts[2 * EDG + e], v);
        v = fmaf(wr[3], fts[3 * EDG + e], v);
        v = fmaf(wr[4], fts[4 * EDG + e], v);
        v = fmaf(wr[5], fts[5 * EDG + e], v);
        y1s[i] = lrelu(v);
    }
    __syncthreads();

    const int og = tid & 7;
    const int eg = tid >> 3;
    const int e0 = eg * 10;
    const int o0 = og * 8;

    float2 acc[5][8];
#pragma unroll
    for (int i = 0; i < 5; i++)
#pragma unroll
        for (int j = 0; j < 8; j++) acc[i][j] = make_float2(0.f, 0.f);

#pragma unroll 1
    for (int m = 0; m < 64; m++) {
        float2 yp[5];
        const float* yr = y1s + m * EDG + e0;
#pragma unroll
        for (int i = 0; i < 5; i++)
            yp[i] = *reinterpret_cast<const float2*>(yr + 2 * i);
#pragma unroll
        for (int c = 0; c < 6; c++) {
            const float* wr = Wp + (m * 6 + c) * 64 + o0;
            float4 wa = *reinterpret_cast<const float4*>(wr);
            float4 wb = *reinterpret_cast<const float4*>(wr + 4);
            float2 wd[8];
            wd[0] = make_float2(wa.x, wa.x); wd[1] = make_float2(wa.y, wa.y);
            wd[2] = make_float2(wa.z, wa.z); wd[3] = make_float2(wa.w, wa.w);
            wd[4] = make_float2(wb.x, wb.x); wd[5] = make_float2(wb.y, wb.y);
            wd[6] = make_float2(wb.z, wb.z); wd[7] = make_float2(wb.w, wb.w);
            const float* fr = fts + c * EDG + e0;
#pragma unroll
            for (int i = 0; i < 5; i++) {
                float2 fp = *reinterpret_cast<const float2*>(fr + 2 * i);
                float2 a  = fmul2(yp[i], fp);
#pragma unroll
                for (int j = 0; j < 8; j++)
                    acc[i][j] = ffma2(a, wd[j], acc[i][j]);
            }
        }
    }

    float pmax[8];
#pragma unroll
    for (int j = 0; j < 8; j++) pmax[j] = -3.4e38f;
#pragma unroll
    for (int j = 0; j < 8; j++) {
        float bb = b1s[o0 + j];
#pragma unroll
        for (int i = 0; i < 5; i++) {
            float vx = lrelu(acc[i][j].x + bb);
            float vy = lrelu(acc[i][j].y + bb);
            pmax[j] = fmaxf(pmax[j], fmaxf(vx, vy));
        }
    }
    const int pt = eg >> 1;
    if ((eg & 1) == 0) {
#pragma unroll
        for (int j = 0; j < 8; j++) x1s[pt * 64 + o0 + j] = pmax[j];
    }
    __syncthreads();
    if (eg & 1) {
#pragma unroll
        for (int j = 0; j < 8; j++) {
            float* p = x1s + pt * 64 + o0 + j;
            *p = fmaxf(*p, pmax[j]);
        }
    }
    __syncthreads();

    if (tid < 48) {
        int oo  = tid >> 4;
        int pt2 = tid & 15;
        const float* wr = w_out + oo * 64;
        const float* xr = x1s + pt2 * 64;
        float s = 0.f;
#pragma unroll
        for (int o = 0; o < 64; o++) s = fmaf(wr[o], xr[o], s);
        float v = s * (g_out[oo] * rsqrtf(1.f + EPSV)) + b_out[oo];
        out[(b * 3 + oo) * NPTS + p0 + pt2] = lrelu(v);
    }
}

// ---------------------------------------------------------------------------
extern "C" void kernel_launch(void* const* d_in, const int* in_sizes, int n_in,
                              void* d_out, int out_size) {
    const float* x     = (const float*)d_in[0];
    const float* w0    = (const float*)d_in[1];
    const float* g0    = (const float*)d_in[2];
    const float* b0    = (const float*)d_in[3];
    const float* w1    = (const float*)d_in[4];
    const float* g1    = (const float*)d_in[5];
    const float* b1    = (const float*)d_in[6];
    const float* w_out = (const float*)d_in[7];
    const float* g_out = (const float*)d_in[8];
    const float* b_out = (const float*)d_in[9];
    float* out = (float*)d_out;

    const int knn_smem  = NPTS * 16 + QPB * BCAP * 8;                       // 73728
    const int main_smem = (24576 + 20480 + 1920 + 1024 + 384 + 64 + 64) * 4;

    cudaFuncSetAttribute(knn_prep_kernel, cudaFuncAttributeMaxDynamicSharedMemorySize,
                         knn_smem);
    cudaFuncSetAttribute(main_kernel, cudaFuncAttributeMaxDynamicSharedMemorySize,
                         main_smem);

    knn_prep_kernel<<<dim3(NPTS / QPB, BATCH), 256, knn_smem>>>(x, w0, g0, w1, g1);
    main_kernel<<<BATCH * (NPTS / PTS), THR, main_smem>>>(x, b0, b1, w_out,
                                                          g_out, b_out, out);
}

// round 10
// speedup vs baseline: 1.6209x; 1.6209x over previous
#include <cuda_runtime.h>
#include <cstdint>

#define BATCH 4
#define NPTS  4096
#define KNB   20
#define EPSV  1e-5f
#define SLOPE 0.2f
#define QPB  8
#define BCAP 128

// main kernel smem layout (float offsets)
#define OF_WPS 0          // 192 rows * 68 * 2 = 26112  (k-pair-interleaved Wp)
#define OF_Y1  26112      // 320 * 66 (y1, later overlaid by z)
#define OF_FT  47232      // 320 * 9
#define OF_X1  50112      // 16 * 64
#define OF_W0  51136      // 384
#define OF_B0  51520      // 64
#define OF_B1  51584      // 64
#define OF_WO  51648      // 192
#define SM_FLOATS 51840   // 207360 bytes

__device__ float g_wb[48 * 4 * 64 * 2];   // tf32 bits, [ks][j][o][par]
__device__ float g_w0f[384];
__device__ int   g_idx[BATCH * NPTS * KNB];

__device__ __forceinline__ float lrelu(float v) { return fmaxf(v, SLOPE * v); }

__device__ __forceinline__ unsigned fkey(float d) {
    unsigned b = __float_as_uint(d);
    return b ^ ((unsigned)((int)b >> 31) | 0x80000000u);
}
__device__ __forceinline__ uint32_t tf32r(float v) {
    uint32_t r; asm("cvt.rna.tf32.f32 %0, %1;" : "=r"(r) : "f"(v)); return r;
}

#define MMA_TF32(d, a0, a1, a2, a3, b0, b1) \
    asm volatile("mma.sync.aligned.m16n8k8.row.col.f32.tf32.tf32.f32 " \
        "{%0,%1,%2,%3}, {%4,%5,%6,%7}, {%8,%9}, {%0,%1,%2,%3};" \
        : "+f"((d)[0]), "+f"((d)[1]), "+f"((d)[2]), "+f"((d)[3]) \
        : "r"(a0), "r"(a1), "r"(a2), "r"(a3), "r"(b0), "r"(b1))

// ---------------------------------------------------------------------------
// KNN (round-7, proven ~115us) + prep of tf32 Wp (k-pair layout) and w0 fold
// ---------------------------------------------------------------------------
__global__ void __launch_bounds__(256, 2) knn_prep_kernel(
    const float* __restrict__ x,
    const float* __restrict__ w0, const float* __restrict__ g0,
    const float* __restrict__ w1, const float* __restrict__ g1)
{
    extern __shared__ char dsm[];
    float4*             pts = reinterpret_cast<float4*>(dsm);
    unsigned long long* buf = reinterpret_cast<unsigned long long*>(dsm + 65536);

    const int tid = threadIdx.x, lane = tid & 31, w = tid >> 5;
    const int b = blockIdx.y, q = blockIdx.x * QPB + w;
    const float* xb = x + b * 3 * NPTS;

    {   // prep distributed over 2048 blocks
        const int gt = (blockIdx.y * gridDim.x + blockIdx.x) * 256 + tid;
        const float inv = rsqrtf(1.f + EPSV);
        if (gt < 384) g_w0f[gt] = w0[gt] * g0[gt / 6] * inv;
        if (gt < 24576) {
            int par = gt & 1, o = (gt >> 1) & 63, jj = (gt >> 7) & 3, ks = gt >> 9;
            int kc = ks * 8 + jj + par * 4;
            int m = kc / 6, c = kc - m * 6;
            float v = g1[o] * inv * w1[(o * 6 + c) * 64 + m];
            g_wb[gt] = __uint_as_float(tf32r(v));
        }
    }

    for (int i = tid; i < NPTS; i += 256) {
        float vx = xb[i], vy = xb[NPTS + i], vz = xb[2 * NPTS + i];
        pts[i] = make_float4(vx, vy, vz, fmaf(vx, vx, fmaf(vy, vy, vz * vz)));
    }
    __syncthreads();

    const float4 qp = pts[q];
    const float qx = qp.x, qy = qp.y, qz = qp.z;
    const float INF = __int_as_float(0x7f800000);

    float m0 = INF, m1 = INF, m2 = INF, m3 = INF;
#pragma unroll 2
    for (int t = 0; t < NPTS / 32; t += 4) {
        float4 p0 = pts[((t + 0) << 5) + lane];
        float4 p1 = pts[((t + 1) << 5) + lane];
        float4 p2 = pts[((t + 2) << 5) + lane];
        float4 p3 = pts[((t + 3) << 5) + lane];
        m0 = fminf(m0, fmaf(-2.f, fmaf(qx, p0.x, fmaf(qy, p0.y, qz * p0.z)), p0.w));
        m1 = fminf(m1, fmaf(-2.f, fmaf(qx, p1.x, fmaf(qy, p1.y, qz * p1.z)), p1.w));
        m2 = fminf(m2, fmaf(-2.f, fmaf(qx, p2.x, fmaf(qy, p2.y, qz * p2.z)), p2.w));
        m3 = fminf(m3, fmaf(-2.f, fmaf(qx, p3.x, fmaf(qy, p3.y, qz * p3.z)), p3.w));
    }
    float val = fminf(fminf(m0, m1), fminf(m2, m3));

    float T = INF;
    for (int r = 0; r < KNB; r++) {
        float wmin = val;
#pragma unroll
        for (int d = 16; d; d >>= 1)
            wmin = fminf(wmin, __shfl_xor_sync(0xffffffffu, wmin, d));
        unsigned msk = __ballot_sync(0xffffffffu, val == wmin);
        if (lane == (__ffs(msk) - 1)) val = INF;
        T = wmin;
    }

    unsigned long long* myb = buf + w * BCAP;
    unsigned nb = 0;
    for (int t = 0; t < NPTS / 32; t++) {
        const int j = (t << 5) + lane;
        float4 p = pts[j];
        float d = fmaf(-2.f, fmaf(qx, p.x, fmaf(qy, p.y, qz * p.z)), p.w);
        bool pass = (d <= T);
        unsigned mask = __ballot_sync(0xffffffffu, pass);
        if (mask) {
            if (pass) {
                unsigned pos = nb + __popc(mask & ((1u << lane) - 1u));
                if (pos < BCAP)
                    myb[pos] = ((unsigned long long)fkey(d) << 32) | (unsigned)j;
            }
            nb += __popc(mask);
        }
    }
    __syncwarp();

    int* obase = g_idx + (b * NPTS + q) * KNB;
    if (nb <= BCAP) {
        unsigned long long v[BCAP / 32];
#pragma unroll
        for (int u = 0; u < BCAP / 32; u++) {
            int t = lane + u * 32;
            v[u] = (t < (int)nb) ? myb[t] : 0xffffffffffffffffull;
        }
        for (int r = 0; r < KNB; r++) {
            unsigned long long lmin = v[0]; int lpos = 0;
#pragma unroll
            for (int u = 1; u < BCAP / 32; u++)
                if (v[u] < lmin) { lmin = v[u]; lpos = u; }
            unsigned long long wmin = lmin;
#pragma unroll
            for (int d = 16; d; d >>= 1) {
                unsigned long long o = __shfl_xor_sync(0xffffffffu, wmin, d);
                wmin = (o < wmin) ? o : wmin;
            }
            if (lmin == wmin) {
#pragma unroll
                for (int u = 0; u < BCAP / 32; u++)
                    if (u == lpos) v[u] = 0xffffffffffffffffull;
            }
            if (lane == 0) obase[r] = (int)(unsigned)(wmin & 0xffffffffull);
        }
    } else {
        unsigned long long last = 0;
        for (int r = 0; r < KNB; r++) {
            unsigned long long best = 0xffffffffffffffffull;
            for (int t = 0; t < NPTS / 32; t++) {
                const int j = (t << 5) + lane;
                float4 p = pts[j];
                float d = fmaf(-2.f, fmaf(qx, p.x, fmaf(qy, p.y, qz * p.z)), p.w);
                unsigned long long kk = ((unsigned long long)fkey(d) << 32) | (unsigned)j;
                if (kk > last && kk < best) best = kk;
            }
#pragma unroll
            for (int d = 16; d; d >>= 1) {
                unsigned long long o = __shfl_xor_sync(0xffffffffu, best, d);
                best = (o < best) ? o : best;
            }
            if (lane == 0) obase[r] = (int)(unsigned)(best & 0xffffffffull);
            last = best;
        }
    }
}

// ---------------------------------------------------------------------------
// Main: tf32 mma.sync (HMMA) GEMM. Block = 16 points = 320 edges, 320 thr.
// Warp w owns M-stripes {w, w+10} (16 edges each), both in one k-loop so each
// B fragment load feeds two MMAs. z = lrelu(D + b1) overlays the warp's own
// y1 rows; then block-wide max over k and the 64->3 output conv.
// ---------------------------------------------------------------------------
__global__ void __launch_bounds__(320, 1) main_mma(
    const float* __restrict__ x,     const float* __restrict__ b0,
    const float* __restrict__ b1,    const float* __restrict__ w_out,
    const float* __restrict__ g_out, const float* __restrict__ b_out,
    float* __restrict__ out)
{
    extern __shared__ float sm[];
    float* wps = sm + OF_WPS;
    float* y1s = sm + OF_Y1;
    float* fts = sm + OF_FT;
    float* x1s = sm + OF_X1;
    float* w0f = sm + OF_W0;
    float* b0s = sm + OF_B0;
    float* b1s = sm + OF_B1;
    float* wos = sm + OF_WO;

    const int tid = threadIdx.x, lane = tid & 31, wid = tid >> 5;
    const int b = blockIdx.y, p0 = blockIdx.x * 16;
    const float* xb = x + b * 3 * NPTS;

    // gather this thread's edge (tid == edge index, 320 exactly)
    float f[6];
    {
        int n = p0 + tid / 20;
        int j = g_idx[(b * NPTS + n) * KNB + tid % 20];
        float xi0 = xb[n], xi1 = xb[NPTS + n], xi2 = xb[2 * NPTS + n];
        float xj0 = xb[j], xj1 = xb[NPTS + j], xj2 = xb[2 * NPTS + j];
        f[0] = xj0 - xi0; f[1] = xj1 - xi1; f[2] = xj2 - xi2;
        f[3] = xi0; f[4] = xi1; f[5] = xi2;
    }
    // Wp -> smem (stride-68 padded rows, conflict-free LDS.64 later)
    for (int g4 = tid; g4 < 6144; g4 += 320) {
        float4 v = reinterpret_cast<const float4*>(g_wb)[g4];
        int t = g4 << 1;
        int o = t & 63, row = t >> 6;
        *reinterpret_cast<float4*>(wps + (row * 68 + o) * 2) = v;
    }
    for (int i = tid; i < 384; i += 320) w0f[i] = g_w0f[i];
    if (tid < 64) { b0s[tid] = b0[tid]; b1s[tid] = b1[tid]; }
    if (tid < 192) wos[tid] = w_out[tid];
#pragma unroll
    for (int i = 0; i < 6; i++) fts[tid * 9 + i] = f[i];
    __syncthreads();

    // y1 row for this edge
    {
        float* yrow = y1s + tid * 66;
#pragma unroll 8
        for (int m = 0; m < 64; m++) {
            const float* wr = w0f + m * 6;
            float v = b0s[m];
            v = fmaf(wr[0], f[0], v); v = fmaf(wr[1], f[1], v);
            v = fmaf(wr[2], f[2], v); v = fmaf(wr[3], f[3], v);
            v = fmaf(wr[4], f[4], v); v = fmaf(wr[5], f[5], v);
            yrow[m] = lrelu(v);
        }
    }
    __syncthreads();

    // ---- GEMM ----
    const int j = lane & 3, q = lane >> 2;
    const int rA = wid * 16 + q;       // stripe wid rows rA, rA+8
    const int rB = rA + 160;           // stripe wid+10

    // ft register cache: c(ks) = (j + 2*(ks%3)) % 6 for kc0; kc1 uses phase+2
    float ftA0[3], ftA8[3], ftB0[3], ftB8[3];
#pragma unroll
    for (int t = 0; t < 3; t++) {
        int c = (j + 2 * t) % 6;
        ftA0[t] = fts[rA * 9 + c];       ftA8[t] = fts[(rA + 8) * 9 + c];
        ftB0[t] = fts[rB * 9 + c];       ftB8[t] = fts[(rB + 8) * 9 + c];
    }

    float dA[8][4], dB[8][4];
#pragma unroll
    for (int nt = 0; nt < 8; nt++)
#pragma unroll
        for (int u = 0; u < 4; u++) { dA[nt][u] = 0.f; dB[nt][u] = 0.f; }

    const float* yA0 = y1s + rA * 66;        const float* yA8 = y1s + (rA + 8) * 66;
    const float* yB0 = y1s + rB * 66;        const float* yB8 = y1s + (rB + 8) * 66;

    for (int ks3 = 0; ks3 < 16; ks3++) {
#pragma unroll
        for (int t = 0; t < 3; t++) {
            const int ks = ks3 * 3 + t;
            const int kc0 = ks * 8 + j;
            const int m0 = kc0 / 6, m1 = (kc0 + 4) / 6;
            const int ph0 = t, ph1 = (t + 2) % 3;

            uint32_t a0 = tf32r(yA0[m0] * ftA0[ph0]);
            uint32_t a1 = tf32r(yA8[m0] * ftA8[ph0]);
            uint32_t a2 = tf32r(yA0[m1] * ftA0[ph1]);
            uint32_t a3 = tf32r(yA8[m1] * ftA8[ph1]);
            uint32_t e0 = tf32r(yB0[m0] * ftB0[ph0]);
            uint32_t e1 = tf32r(yB8[m0] * ftB8[ph0]);
            uint32_t e2 = tf32r(yB0[m1] * ftB0[ph1]);
            uint32_t e3 = tf32r(yB8[m1] * ftB8[ph1]);

            const float* wrow = wps + ((ks * 4 + j) * 68 + q) * 2;
#pragma unroll
            for (int nt = 0; nt < 8; nt++) {
                float2 bb = *reinterpret_cast<const float2*>(wrow + nt * 16);
                uint32_t b0r = __float_as_uint(bb.x), b1r = __float_as_uint(bb.y);
                MMA_TF32(dA[nt], a0, a1, a2, a3, b0r, b1r);
                MMA_TF32(dB[nt], e0, e1, e2, e3, b0r, b1r);
            }
        }
    }

    // z = lrelu(D + b1) overlays this warp's own y1 rows
    __syncwarp();
#pragma unroll
    for (int nt = 0; nt < 8; nt++) {
        int c = nt * 8 + j * 2;
        float bc0 = b1s[c], bc1 = b1s[c + 1];
        float2 zA01 = make_float2(lrelu(dA[nt][0] + bc0), lrelu(dA[nt][1] + bc1));
        float2 zA23 = make_float2(lrelu(dA[nt][2] + bc0), lrelu(dA[nt][3] + bc1));
        float2 zB01 = make_float2(lrelu(dB[nt][0] + bc0), lrelu(dB[nt][1] + bc1));
        float2 zB23 = make_float2(lrelu(dB[nt][2] + bc0), lrelu(dB[nt][3] + bc1));
        *reinterpret_cast<float2*>(y1s + rA * 66 + c)       = zA01;
        *reinterpret_cast<float2*>(y1s + (rA + 8) * 66 + c) = zA23;
        *reinterpret_cast<float2*>(y1s + rB * 66 + c)       = zB01;
        *reinterpret_cast<float2*>(y1s + (rB + 8) * 66 + c) = zB23;
    }
    __syncthreads();

    // max over k per (point, col)
    for (int it = tid; it < 16 * 64; it += 320) {
        int p = it >> 6, col = it & 63;
        const float* zr = y1s + (p * 20) * 66 + col;
        float m = -3.4e38f;
#pragma unroll
        for (int kk = 0; kk < 20; kk++) m = fmaxf(m, zr[kk * 66]);
        x1s[it] = m;
    }
    __syncthreads();

    // final conv: out = lrelu(gout*inv*(w_out @ x1) + bout)
    if (tid < 48) {
        int oo = tid >> 4, pt = tid & 15;
        const float* wr = wos + oo * 64;
        const float* xr = x1s + pt * 64;
        float s = 0.f;
#pragma unroll
        for (int o = 0; o < 64; o++) s = fmaf(wr[o], xr[o], s);
        float v = s * (g_out[oo] * rsqrtf(1.f + EPSV)) + b_out[oo];
        out[(b * 3 + oo) * NPTS + p0 + pt] = lrelu(v);
    }
}

// ---------------------------------------------------------------------------
extern "C" void kernel_launch(void* const* d_in, const int* in_sizes, int n_in,
                              void* d_out, int out_size) {
    const float* x     = (const float*)d_in[0];
    const float* w0    = (const float*)d_in[1];
    const float* g0    = (const float*)d_in[2];
    const float* b0    = (const float*)d_in[3];
    const float* w1    = (const float*)d_in[4];
    const float* g1    = (const float*)d_in[5];
    const float* b1    = (const float*)d_in[6];
    const float* w_out = (const float*)d_in[7];
    const float* g_out = (const float*)d_in[8];
    const float* b_out = (const float*)d_in[9];
    float* out = (float*)d_out;

    const int knn_smem  = NPTS * 16 + QPB * BCAP * 8;   // 73728
    const int main_smem = SM_FLOATS * 4;                // 207360

    cudaFuncSetAttribute(knn_prep_kernel, cudaFuncAttributeMaxDynamicSharedMemorySize,
                         knn_smem);
    cudaFuncSetAttribute(main_mma, cudaFuncAttributeMaxDynamicSharedMemorySize,
                         main_smem);

    knn_prep_kernel<<<dim3(NPTS / QPB, BATCH), 256, knn_smem>>>(x, w0, g0, w1, g1);
    main_mma<<<dim3(NPTS / 16, BATCH), 320, main_smem>>>(x, b0, b1, w_out,
                                                         g_out, b_out, out);
}

// round 11
// speedup vs baseline: 1.7293x; 1.0669x over previous
#include <cuda_runtime.h>
#include <cstdint>

#define BATCH 4
#define NPTS  4096
#define KNB   20
#define EPSV  1e-5f
#define SLOPE 0.2f
#define QPB  8
#define BCAP 128

// main kernel smem layout (float offsets)
#define OF_WPS 0          // 192 rows * 68 * 2 = 26112  (k-pair-interleaved Wp)
#define OF_Y1  26112      // 320 * 66 (y1, later overlaid by z)
#define OF_FT  47232      // 320 * 9
#define OF_X1  50112      // 16 * 64
#define OF_W0  51136      // 384
#define OF_B0  51520      // 64
#define OF_B1  51584      // 64
#define OF_WO  51648      // 192
#define SM_FLOATS 51840   // 207360 bytes

__device__ float g_wb[48 * 4 * 64 * 2];   // tf32 bits, [ks][j][o][par]
__device__ float g_w0f[384];
__device__ int   g_idx[BATCH * NPTS * KNB];

__device__ __forceinline__ float lrelu(float v) { return fmaxf(v, SLOPE * v); }

__device__ __forceinline__ unsigned fkey(float d) {
    unsigned b = __float_as_uint(d);
    return b ^ ((unsigned)((int)b >> 31) | 0x80000000u);
}
__device__ __forceinline__ uint32_t tf32r(float v) {
    uint32_t r; asm("cvt.rna.tf32.f32 %0, %1;" : "=r"(r) : "f"(v)); return r;
}

#define MMA_TF32(d, a0, a1, a2, a3, b0, b1) \
    asm volatile("mma.sync.aligned.m16n8k8.row.col.f32.tf32.tf32.f32 " \
        "{%0,%1,%2,%3}, {%4,%5,%6,%7}, {%8,%9}, {%0,%1,%2,%3};" \
        : "+f"((d)[0]), "+f"((d)[1]), "+f"((d)[2]), "+f"((d)[3]) \
        : "r"(a0), "r"(a1), "r"(a2), "r"(a3), "r"(b0), "r"(b1))

// ---------------------------------------------------------------------------
// KNN (threshold-filter, atomic compaction) + prep of tf32 Wp and w0 fold
// ---------------------------------------------------------------------------
__global__ void __launch_bounds__(256, 2) knn_prep_kernel(
    const float* __restrict__ x,
    const float* __restrict__ w0, const float* __restrict__ g0,
    const float* __restrict__ w1, const float* __restrict__ g1)
{
    extern __shared__ char dsm[];
    float4*             pts = reinterpret_cast<float4*>(dsm);
    unsigned long long* buf = reinterpret_cast<unsigned long long*>(dsm + 65536);
    unsigned*           cnt = reinterpret_cast<unsigned*>(dsm + 65536 + QPB * BCAP * 8);

    const int tid = threadIdx.x, lane = tid & 31, w = tid >> 5;
    const int b = blockIdx.y, q = blockIdx.x * QPB + w;
    const float* xb = x + b * 3 * NPTS;

    {   // prep distributed over 2048 blocks
        const int gt = (blockIdx.y * gridDim.x + blockIdx.x) * 256 + tid;
        const float inv = rsqrtf(1.f + EPSV);
        if (gt < 384) g_w0f[gt] = w0[gt] * g0[gt / 6] * inv;
        if (gt < 24576) {
            int par = gt & 1, o = (gt >> 1) & 63, jj = (gt >> 7) & 3, ks = gt >> 9;
            int kc = ks * 8 + jj + par * 4;
            int m = kc / 6, c = kc - m * 6;
            float v = g1[o] * inv * w1[(o * 6 + c) * 64 + m];
            g_wb[gt] = __uint_as_float(tf32r(v));
        }
    }

    for (int i = tid; i < NPTS; i += 256) {
        float vx = xb[i], vy = xb[NPTS + i], vz = xb[2 * NPTS + i];
        pts[i] = make_float4(vx, vy, vz, fmaf(vx, vx, fmaf(vy, vy, vz * vz)));
    }
    if (tid < QPB) cnt[tid] = 0;
    __syncthreads();

    const float4 qp = pts[q];
    const float qx = qp.x, qy = qp.y, qz = qp.z;
    const float INF = __int_as_float(0x7f800000);

    // ---- pass 1: branchless per-lane min, 8 independent chains ----
    float mn[8];
#pragma unroll
    for (int u = 0; u < 8; u++) mn[u] = INF;
    for (int t = 0; t < NPTS / 32; t += 8) {
#pragma unroll
        for (int u = 0; u < 8; u++) {
            float4 p = pts[((t + u) << 5) + lane];
            mn[u] = fminf(mn[u],
                fmaf(-2.f, fmaf(qx, p.x, fmaf(qy, p.y, qz * p.z)), p.w));
        }
    }
    float val = fminf(fminf(fminf(mn[0], mn[1]), fminf(mn[2], mn[3])),
                      fminf(fminf(mn[4], mn[5]), fminf(mn[6], mn[7])));

    // ---- threshold: T = 20th smallest lane-min (with multiplicity) ----
    float T = INF;
    for (int r = 0; r < KNB; r++) {
        float wmin = val;
#pragma unroll
        for (int d = 16; d; d >>= 1)
            wmin = fminf(wmin, __shfl_xor_sync(0xffffffffu, wmin, d));
        unsigned msk = __ballot_sync(0xffffffffu, val == wmin);
        if (lane == (__ffs(msk) - 1)) val = INF;
        T = wmin;
    }

    // ---- pass 2: compact passers via rare shared atomic (order irrelevant:
    //      keys embed idx, phase-3 selection is order-independent) ----
    unsigned long long* myb = buf + w * BCAP;
    for (int t = 0; t < NPTS / 32; t++) {
        const int j = (t << 5) + lane;
        float4 p = pts[j];
        float d = fmaf(-2.f, fmaf(qx, p.x, fmaf(qy, p.y, qz * p.z)), p.w);
        if (d <= T) {
            unsigned pos = atomicAdd(&cnt[w], 1u);
            if (pos < BCAP)
                myb[pos] = ((unsigned long long)fkey(d) << 32) | (unsigned)j;
        }
    }
    __syncwarp();
    const unsigned nb = cnt[w];

    // ---- phase 3: exact top-20 (nb >= 20 guaranteed by threshold rule) ----
    int* obase = g_idx + (b * NPTS + q) * KNB;
    if (nb <= BCAP) {
        unsigned long long v[BCAP / 32];
#pragma unroll
        for (int u = 0; u < BCAP / 32; u++) {
            int t = lane + u * 32;
            v[u] = (t < (int)nb) ? myb[t] : 0xffffffffffffffffull;
        }
        for (int r = 0; r < KNB; r++) {
            unsigned long long lmin = v[0]; int lpos = 0;
#pragma unroll
            for (int u = 1; u < BCAP / 32; u++)
                if (v[u] < lmin) { lmin = v[u]; lpos = u; }
            unsigned long long wmin = lmin;
#pragma unroll
            for (int d = 16; d; d >>= 1) {
                unsigned long long o = __shfl_xor_sync(0xffffffffu, wmin, d);
                wmin = (o < wmin) ? o : wmin;
            }
            if (lmin == wmin) {
#pragma unroll
                for (int u = 0; u < BCAP / 32; u++)
                    if (u == lpos) v[u] = 0xffffffffffffffffull;
            }
            if (lane == 0) obase[r] = (int)(unsigned)(wmin & 0xffffffffull);
        }
    } else {
        unsigned long long last = 0;
        for (int r = 0; r < KNB; r++) {
            unsigned long long best = 0xffffffffffffffffull;
            for (int t = 0; t < NPTS / 32; t++) {
                const int j = (t << 5) + lane;
                float4 p = pts[j];
                float d = fmaf(-2.f, fmaf(qx, p.x, fmaf(qy, p.y, qz * p.z)), p.w);
                unsigned long long kk = ((unsigned long long)fkey(d) << 32) | (unsigned)j;
                if (kk > last && kk < best) best = kk;
            }
#pragma unroll
            for (int d = 16; d; d >>= 1) {
                unsigned long long o = __shfl_xor_sync(0xffffffffu, best, d);
                best = (o < best) ? o : best;
            }
            if (lane == 0) obase[r] = (int)(unsigned)(best & 0xffffffffull);
            last = best;
        }
    }
}

// ---------------------------------------------------------------------------
// Main: tf32 mma.sync GEMM, 640 threads (20 warps), warp = one 16-edge
// M-stripe, full K=384, N=64. Same numerics as round 10; doubled occupancy.
// ---------------------------------------------------------------------------
__global__ void __launch_bounds__(640, 1) main_mma(
    const float* __restrict__ x,     const float* __restrict__ b0,
    const float* __restrict__ b1,    const float* __restrict__ w_out,
    const float* __restrict__ g_out, const float* __restrict__ b_out,
    float* __restrict__ out)
{
    extern __shared__ float sm[];
    float* wps = sm + OF_WPS;
    float* y1s = sm + OF_Y1;
    float* fts = sm + OF_FT;
    float* x1s = sm + OF_X1;
    float* w0f = sm + OF_W0;
    float* b0s = sm + OF_B0;
    float* b1s = sm + OF_B1;
    float* wos = sm + OF_WO;

    const int tid = threadIdx.x, lane = tid & 31, wid = tid >> 5;
    const int b = blockIdx.y, p0 = blockIdx.x * 16;
    const float* xb = x + b * 3 * NPTS;

    // thread pair (2e, 2e+1) handles edge e: gather f, split y1 m-range
    const int e  = tid >> 1;          // 0..319
    const int mh = (tid & 1) * 32;    // m half
    float f[6];
    {
        int n = p0 + e / 20;
        int jn = g_idx[(b * NPTS + n) * KNB + e % 20];
        float xi0 = xb[n],  xi1 = xb[NPTS + n],  xi2 = xb[2 * NPTS + n];
        float xj0 = xb[jn], xj1 = xb[NPTS + jn], xj2 = xb[2 * NPTS + jn];
        f[0] = xj0 - xi0; f[1] = xj1 - xi1; f[2] = xj2 - xi2;
        f[3] = xi0; f[4] = xi1; f[5] = xi2;
    }
    // Wp -> smem (stride-68 padded rows)
    for (int g4 = tid; g4 < 6144; g4 += 640) {
        float4 v = reinterpret_cast<const float4*>(g_wb)[g4];
        int t = g4 << 1;
        int o = t & 63, row = t >> 6;
        *reinterpret_cast<float4*>(wps + (row * 68 + o) * 2) = v;
    }
    if (tid < 384) w0f[tid] = g_w0f[tid];
    if (tid < 64) { b0s[tid] = b0[tid]; b1s[tid] = b1[tid]; }
    if (tid < 192) wos[tid] = w_out[tid];
    if ((tid & 1) == 0) {
#pragma unroll
        for (int i = 0; i < 6; i++) fts[e * 9 + i] = f[i];
    }
    __syncthreads();

    // y1: 32 m values per thread of the pair
    {
        float* yrow = y1s + e * 66;
#pragma unroll 8
        for (int mm = 0; mm < 32; mm++) {
            int m = mh + mm;
            const float* wr = w0f + m * 6;
            float v = b0s[m];
            v = fmaf(wr[0], f[0], v); v = fmaf(wr[1], f[1], v);
            v = fmaf(wr[2], f[2], v); v = fmaf(wr[3], f[3], v);
            v = fmaf(wr[4], f[4], v); v = fmaf(wr[5], f[5], v);
            yrow[m] = lrelu(v);
        }
    }
    __syncthreads();

    // ---- GEMM: warp wid owns rows [wid*16, wid*16+16) ----
    const int j = lane & 3, q = lane >> 2;
    const int rA = wid * 16 + q;

    float ft0[3], ft8[3];
#pragma unroll
    for (int t = 0; t < 3; t++) {
        int c = (j + 2 * t) % 6;
        ft0[t] = fts[rA * 9 + c];
        ft8[t] = fts[(rA + 8) * 9 + c];
    }

    float dA[8][4];
#pragma unroll
    for (int nt = 0; nt < 8; nt++)
#pragma unroll
        for (int u = 0; u < 4; u++) dA[nt][u] = 0.f;

    const float* yA0 = y1s + rA * 66;
    const float* yA8 = y1s + (rA + 8) * 66;

    for (int ks3 = 0; ks3 < 16; ks3++) {
#pragma unroll
        for (int t = 0; t < 3; t++) {
            const int ks = ks3 * 3 + t;
            const int kc0 = ks * 8 + j;
            const int m0 = kc0 / 6, m1 = (kc0 + 4) / 6;
            const int ph1 = (t + 2) % 3;

            uint32_t a0 = tf32r(yA0[m0] * ft0[t]);
            uint32_t a1 = tf32r(yA8[m0] * ft8[t]);
            uint32_t a2 = tf32r(yA0[m1] * ft0[ph1]);
            uint32_t a3 = tf32r(yA8[m1] * ft8[ph1]);

            const float* wrow = wps + ((ks * 4 + j) * 68 + q) * 2;
#pragma unroll
            for (int nt = 0; nt < 8; nt++) {
                float2 bb = *reinterpret_cast<const float2*>(wrow + nt * 16);
                uint32_t b0r = __float_as_uint(bb.x), b1r = __float_as_uint(bb.y);
                MMA_TF32(dA[nt], a0, a1, a2, a3, b0r, b1r);
            }
        }
    }

    // z = lrelu(D + b1) overlays this warp's own y1 rows
    __syncwarp();
#pragma unroll
    for (int nt = 0; nt < 8; nt++) {
        int c = nt * 8 + j * 2;
        float bc0 = b1s[c], bc1 = b1s[c + 1];
        *reinterpret_cast<float2*>(y1s + rA * 66 + c) =
            make_float2(lrelu(dA[nt][0] + bc0), lrelu(dA[nt][1] + bc1));
        *reinterpret_cast<float2*>(y1s + (rA + 8) * 66 + c) =
            make_float2(lrelu(dA[nt][2] + bc0), lrelu(dA[nt][3] + bc1));
    }
    __syncthreads();

    // max over k per (point, col)
    for (int it = tid; it < 16 * 64; it += 640) {
        int p = it >> 6, col = it & 63;
        const float* zr = y1s + (p * 20) * 66 + col;
        float m = -3.4e38f;
#pragma unroll
        for (int kk = 0; kk < 20; kk++) m = fmaxf(m, zr[kk * 66]);
        x1s[it] = m;
    }
    __syncthreads();

    // final conv: out = lrelu(gout*inv*(w_out @ x1) + bout)
    if (tid < 48) {
        int oo = tid >> 4, pt = tid & 15;
        const float* wr = wos + oo * 64;
        const float* xr = x1s + pt * 64;
        float s = 0.f;
#pragma unroll
        for (int o = 0; o < 64; o++) s = fmaf(wr[o], xr[o], s);
        float v = s * (g_out[oo] * rsqrtf(1.f + EPSV)) + b_out[oo];
        out[(b * 3 + oo) * NPTS + p0 + pt] = lrelu(v);
    }
}

// ---------------------------------------------------------------------------
extern "C" void kernel_launch(void* const* d_in, const int* in_sizes, int n_in,
                              void* d_out, int out_size) {
    const float* x     = (const float*)d_in[0];
    const float* w0    = (const float*)d_in[1];
    const float* g0    = (const float*)d_in[2];
    const float* b0    = (const float*)d_in[3];
    const float* w1    = (const float*)d_in[4];
    const float* g1    = (const float*)d_in[5];
    const float* b1    = (const float*)d_in[6];
    const float* w_out = (const float*)d_in[7];
    const float* g_out = (const float*)d_in[8];
    const float* b_out = (const float*)d_in[9];
    float* out = (float*)d_out;

    const int knn_smem  = NPTS * 16 + QPB * BCAP * 8 + 32;   // 73760
    const int main_smem = SM_FLOATS * 4;                     // 207360

    cudaFuncSetAttribute(knn_prep_kernel, cudaFuncAttributeMaxDynamicSharedMemorySize,
                         knn_smem);
    cudaFuncSetAttribute(main_mma, cudaFuncAttributeMaxDynamicSharedMemorySize,
                         main_smem);

    knn_prep_kernel<<<dim3(NPTS / QPB, BATCH), 256, knn_smem>>>(x, w0, g0, w1, g1);
    main_mma<<<dim3(NPTS / 16, BATCH), 640, main_smem>>>(x, b0, b1, w_out,
                                                         g_out, b_out, out);
}

// round 12
// speedup vs baseline: 1.8731x; 1.0832x over previous
#include <cuda_runtime.h>
#include <cstdint>

#define BATCH 4
#define NPTS  4096
#define KNB   20
#define EPSV  1e-5f
#define SLOPE 0.2f
#define QPB  16
#define BCAP 128

// main kernel smem layout (float offsets)
#define OF_WPS 0          // 192 rows * 66 f2 * 2 = 25344 (o-interleaved Wp)
#define OF_Z   25344      // 320 * 66  (z epilogue buffer)
#define OF_FT  46464      // 320 * 9
#define OF_X1  49344      // 16 * 64
#define OF_W0  50368      // 384
#define OF_B0  50752      // 64
#define OF_B1  50816      // 64
#define OF_WO  50880      // 192
#define SM_FLOATS 51072   // 204288 bytes

__device__ float g_wb[48 * 4 * 64 * 2];   // tf32 bits: [ks][j][i'][par]
__device__ float g_w0f[384];
__device__ int   g_idx[BATCH * NPTS * KNB];

__device__ __forceinline__ float lrelu(float v) { return fmaxf(v, SLOPE * v); }

__device__ __forceinline__ unsigned fkey(float d) {
    unsigned b = __float_as_uint(d);
    return b ^ ((unsigned)((int)b >> 31) | 0x80000000u);
}
__device__ __forceinline__ uint32_t tf32r(float v) {
    uint32_t r; asm("cvt.rna.tf32.f32 %0, %1;" : "=r"(r) : "f"(v)); return r;
}

#define MMA_TF32(d, a0, a1, a2, a3, b0, b1) \
    asm volatile("mma.sync.aligned.m16n8k8.row.col.f32.tf32.tf32.f32 " \
        "{%0,%1,%2,%3}, {%4,%5,%6,%7}, {%8,%9}, {%0,%1,%2,%3};" \
        : "+f"((d)[0]), "+f"((d)[1]), "+f"((d)[2]), "+f"((d)[3]) \
        : "r"(a0), "r"(a1), "r"(a2), "r"(a3), "r"(b0), "r"(b1))

// ---------------------------------------------------------------------------
// KNN (threshold-filter) 16 queries/block + prep of tf32 Wp and w0 fold
// ---------------------------------------------------------------------------
__global__ void __launch_bounds__(512, 2) knn_prep_kernel(
    const float* __restrict__ x,
    const float* __restrict__ w0, const float* __restrict__ g0,
    const float* __restrict__ w1, const float* __restrict__ g1)
{
    extern __shared__ char dsm[];
    float4*             pts = reinterpret_cast<float4*>(dsm);
    unsigned long long* buf = reinterpret_cast<unsigned long long*>(dsm + 65536);
    unsigned*           cnt = reinterpret_cast<unsigned*>(dsm + 65536 + QPB * BCAP * 8);

    const int tid = threadIdx.x, lane = tid & 31, w = tid >> 5;
    const int b = blockIdx.y, q = blockIdx.x * QPB + w;
    const float* xb = x + b * 3 * NPTS;

    {   // prep: [ks][j][i'][par], o = (i'>>3) + (i'&7)*8
        const int gt = (blockIdx.y * gridDim.x + blockIdx.x) * 512 + tid;
        const float inv = rsqrtf(1.f + EPSV);
        if (gt < 384) g_w0f[gt] = w0[gt] * g0[gt / 6] * inv;
        if (gt < 24576) {
            int par = gt & 1, ip = (gt >> 1) & 63, jj = (gt >> 7) & 3, ks = gt >> 9;
            int o  = (ip >> 3) + (ip & 7) * 8;
            int kc = ks * 8 + jj + par * 4;
            int m = kc / 6, c = kc - m * 6;
            float v = g1[o] * inv * w1[(o * 6 + c) * 64 + m];
            g_wb[gt] = __uint_as_float(tf32r(v));
        }
    }

    for (int i = tid; i < NPTS; i += 512) {
        float vx = xb[i], vy = xb[NPTS + i], vz = xb[2 * NPTS + i];
        pts[i] = make_float4(vx, vy, vz, fmaf(vx, vx, fmaf(vy, vy, vz * vz)));
    }
    if (tid < QPB) cnt[tid] = 0;
    __syncthreads();

    const float4 qp = pts[q];
    const float qx = qp.x, qy = qp.y, qz = qp.z;
    const float INF = __int_as_float(0x7f800000);

    // pass 1: branchless per-lane min, 8 independent chains
    float mn[8];
#pragma unroll
    for (int u = 0; u < 8; u++) mn[u] = INF;
    for (int t = 0; t < NPTS / 32; t += 8) {
#pragma unroll
        for (int u = 0; u < 8; u++) {
            float4 p = pts[((t + u) << 5) + lane];
            mn[u] = fminf(mn[u],
                fmaf(-2.f, fmaf(qx, p.x, fmaf(qy, p.y, qz * p.z)), p.w));
        }
    }
    float val = fminf(fminf(fminf(mn[0], mn[1]), fminf(mn[2], mn[3])),
                      fminf(fminf(mn[4], mn[5]), fminf(mn[6], mn[7])));

    // threshold: T = 20th smallest lane-min (with multiplicity)
    float T = INF;
    for (int r = 0; r < KNB; r++) {
        float wmin = val;
#pragma unroll
        for (int d = 16; d; d >>= 1)
            wmin = fminf(wmin, __shfl_xor_sync(0xffffffffu, wmin, d));
        unsigned msk = __ballot_sync(0xffffffffu, val == wmin);
        if (lane == (__ffs(msk) - 1)) val = INF;
        T = wmin;
    }

    // pass 2: compact passers (order irrelevant; keys embed idx)
    unsigned long long* myb = buf + w * BCAP;
    for (int t = 0; t < NPTS / 32; t++) {
        const int j = (t << 5) + lane;
        float4 p = pts[j];
        float d = fmaf(-2.f, fmaf(qx, p.x, fmaf(qy, p.y, qz * p.z)), p.w);
        if (d <= T) {
            unsigned pos = atomicAdd(&cnt[w], 1u);
            if (pos < BCAP)
                myb[pos] = ((unsigned long long)fkey(d) << 32) | (unsigned)j;
        }
    }
    __syncwarp();
    const unsigned nb = cnt[w];

    // phase 3: exact top-20 (nb >= 20 guaranteed)
    int* obase = g_idx + (b * NPTS + q) * KNB;
    if (nb <= BCAP) {
        unsigned long long v[BCAP / 32];
#pragma unroll
        for (int u = 0; u < BCAP / 32; u++) {
            int t = lane + u * 32;
            v[u] = (t < (int)nb) ? myb[t] : 0xffffffffffffffffull;
        }
        for (int r = 0; r < KNB; r++) {
            unsigned long long lmin = v[0]; int lpos = 0;
#pragma unroll
            for (int u = 1; u < BCAP / 32; u++)
                if (v[u] < lmin) { lmin = v[u]; lpos = u; }
            unsigned long long wmin = lmin;
#pragma unroll
            for (int d = 16; d; d >>= 1) {
                unsigned long long o = __shfl_xor_sync(0xffffffffu, wmin, d);
                wmin = (o < wmin) ? o : wmin;
            }
            if (lmin == wmin) {
#pragma unroll
                for (int u = 0; u < BCAP / 32; u++)
                    if (u == lpos) v[u] = 0xffffffffffffffffull;
            }
            if (lane == 0) obase[r] = (int)(unsigned)(wmin & 0xffffffffull);
        }
    } else {
        unsigned long long last = 0;
        for (int r = 0; r < KNB; r++) {
            unsigned long long best = 0xffffffffffffffffull;
            for (int t = 0; t < NPTS / 32; t++) {
                const int j = (t << 5) + lane;
                float4 p = pts[j];
                float d = fmaf(-2.f, fmaf(qx, p.x, fmaf(qy, p.y, qz * p.z)), p.w);
                unsigned long long kk = ((unsigned long long)fkey(d) << 32) | (unsigned)j;
                if (kk > last && kk < best) best = kk;
            }
#pragma unroll
            for (int d = 16; d; d >>= 1) {
                unsigned long long o = __shfl_xor_sync(0xffffffffu, best, d);
                best = (o < best) ? o : best;
            }
            if (lane == 0) obase[r] = (int)(unsigned)(best & 0xffffffffull);
            last = best;
        }
    }
}

// ---------------------------------------------------------------------------
// Main: tf32 mma.sync GEMM, 640 thr / 20 warps, warp = 16-edge M-stripe.
// y operand register-distributed (shfl.idx), zero y-LDS in the GEMM loop.
// B fragments: o-interleaved Wp rows (stride 66 f2), conflict-free LDS.128.
// ---------------------------------------------------------------------------
__global__ void __launch_bounds__(640, 1) main_mma(
    const float* __restrict__ x,     const float* __restrict__ b0,
    const float* __restrict__ b1,    const float* __restrict__ w_out,
    const float* __restrict__ g_out, const float* __restrict__ b_out,
    float* __restrict__ out)
{
    extern __shared__ float sm[];
    float* wps = sm + OF_WPS;
    float* zs  = sm + OF_Z;
    float* fts = sm + OF_FT;
    float* x1s = sm + OF_X1;
    float* w0f = sm + OF_W0;
    float* b0s = sm + OF_B0;
    float* b1s = sm + OF_B1;
    float* wos = sm + OF_WO;

    const int tid = threadIdx.x, lane = tid & 31, wid = tid >> 5;
    const int b = blockIdx.y, p0 = blockIdx.x * 16;
    const float* xb = x + b * 3 * NPTS;

    // edge gather: thread t<320 gathers edge t
    if (tid < 320) {
        int n = p0 + tid / 20;
        int jn = g_idx[(b * NPTS + n) * KNB + tid % 20];
        float xi0 = xb[n],  xi1 = xb[NPTS + n],  xi2 = xb[2 * NPTS + n];
        float xj0 = xb[jn], xj1 = xb[NPTS + jn], xj2 = xb[2 * NPTS + jn];
        float* fr = fts + tid * 9;
        fr[0] = xj0 - xi0; fr[1] = xj1 - xi1; fr[2] = xj2 - xi2;
        fr[3] = xi0; fr[4] = xi1; fr[5] = xi2;
    }
    // Wp -> smem, row stride 66 float2
    for (int g4 = tid; g4 < 6144; g4 += 640) {
        float4 v = reinterpret_cast<const float4*>(g_wb)[g4];
        int t = g4 << 1;
        int ip = t & 63, row = t >> 6;
        *reinterpret_cast<float4*>(wps + row * 132 + ip * 2) = v;
    }
    if (tid < 384) w0f[tid] = g_w0f[tid];
    if (tid < 64) { b0s[tid] = b0[tid]; b1s[tid] = b1[tid]; }
    if (tid < 192) wos[tid] = w_out[tid];
    __syncthreads();

    const int s = lane & 3, q = lane >> 2;
    const int rA = wid * 16 + q;

    // register-distributed y: lane (s,q) holds y[rA][4k+s], y[rA+8][4k+s]
    float yr0[16], yr1[16];
    {
        const float* fA = fts + rA * 9;
        const float* fB = fts + (rA + 8) * 9;
        float a0 = fA[0], a1 = fA[1], a2 = fA[2], a3 = fA[3], a4 = fA[4], a5 = fA[5];
        float c0 = fB[0], c1 = fB[1], c2 = fB[2], c3 = fB[3], c4 = fB[4], c5 = fB[5];
#pragma unroll
        for (int k = 0; k < 16; k++) {
            int m = 4 * k + s;
            const float* wr = w0f + m * 6;
            float bb = b0s[m];
            float u = bb, v = bb;
            u = fmaf(wr[0], a0, u); v = fmaf(wr[0], c0, v);
            u = fmaf(wr[1], a1, u); v = fmaf(wr[1], c1, v);
            u = fmaf(wr[2], a2, u); v = fmaf(wr[2], c2, v);
            u = fmaf(wr[3], a3, u); v = fmaf(wr[3], c3, v);
            u = fmaf(wr[4], a4, u); v = fmaf(wr[4], c4, v);
            u = fmaf(wr[5], a5, u); v = fmaf(wr[5], c5, v);
            yr0[k] = lrelu(u);
            yr1[k] = lrelu(v);
        }
    }

    // ft phase cache for own rows: c(t) = (s + 2t) % 6
    float ft0[3], ft8[3];
#pragma unroll
    for (int t = 0; t < 3; t++) {
        int c = (s + 2 * t) % 6;
        ft0[t] = fts[rA * 9 + c];
        ft8[t] = fts[(rA + 8) * 9 + c];
    }

    float dA[8][4];
#pragma unroll
    for (int nt = 0; nt < 8; nt++)
#pragma unroll
        for (int u = 0; u < 4; u++) dA[nt][u] = 0.f;

    const int qb = q << 2;     // q*4, shfl source base

#pragma unroll 1
    for (int ks3 = 0; ks3 < 16; ks3++) {
#pragma unroll
        for (int t = 0; t < 3; t++) {
            const int ks = ks3 * 3 + t;
            const int kc0 = ks * 8 + s;                 // per-lane
            const int m0 = kc0 / 6, m1 = (kc0 + 4) / 6; // per-lane
            const int r0 = ((ks * 8) / 6) >> 2;         // warp-uniform, compile-time
            const int r1 = ((ks * 8 + 4) / 6) >> 2;     // warp-uniform, compile-time
            const int ph1 = (t + 2) % 3;

            float ya0 = __shfl_sync(0xffffffffu, yr0[r0], qb + (m0 & 3));
            float ya1 = __shfl_sync(0xffffffffu, yr1[r0], qb + (m0 & 3));
            float ya2 = __shfl_sync(0xffffffffu, yr0[r1], qb + (m1 & 3));
            float ya3 = __shfl_sync(0xffffffffu, yr1[r1], qb + (m1 & 3));

            uint32_t a0 = tf32r(ya0 * ft0[t]);
            uint32_t a1 = tf32r(ya1 * ft8[t]);
            uint32_t a2 = tf32r(ya2 * ft0[ph1]);
            uint32_t a3 = tf32r(ya3 * ft8[ph1]);

            const float4* wrow = reinterpret_cast<const float4*>(
                wps + (ks * 4 + s) * 132 + q * 16);
#pragma unroll
            for (int nt2 = 0; nt2 < 4; nt2++) {
                float4 bb = wrow[nt2];
                uint32_t bx = __float_as_uint(bb.x), by = __float_as_uint(bb.y);
                uint32_t bz = __float_as_uint(bb.z), bw = __float_as_uint(bb.w);
                MMA_TF32(dA[nt2 * 2],     a0, a1, a2, a3, bx, by);
                MMA_TF32(dA[nt2 * 2 + 1], a0, a1, a2, a3, bz, bw);
            }
        }
    }

    // z = lrelu(D + b1) -> zs rows (D col = nt*8 + s*2)
    __syncwarp();
#pragma unroll
    for (int nt = 0; nt < 8; nt++) {
        int c = nt * 8 + s * 2;
        float bc0 = b1s[c], bc1 = b1s[c + 1];
        *reinterpret_cast<float2*>(zs + rA * 66 + c) =
            make_float2(lrelu(dA[nt][0] + bc0), lrelu(dA[nt][1] + bc1));
        *reinterpret_cast<float2*>(zs + (rA + 8) * 66 + c) =
            make_float2(lrelu(dA[nt][2] + bc0), lrelu(dA[nt][3] + bc1));
    }
    __syncthreads();

    // max over k per (point, col)
    for (int it = tid; it < 16 * 64; it += 640) {
        int p = it >> 6, col = it & 63;
        const float* zr = zs + (p * 20) * 66 + col;
        float m = -3.4e38f;
#pragma unroll
        for (int kk = 0; kk < 20; kk++) m = fmaxf(m, zr[kk * 66]);
        x1s[it] = m;
    }
    __syncthreads();

    // final conv: out = lrelu(gout*inv*(w_out @ x1) + bout)
    if (tid < 48) {
        int oo = tid >> 4, pt = tid & 15;
        const float* wr = wos + oo * 64;
        const float* xr = x1s + pt * 64;
        float sum = 0.f;
#pragma unroll
        for (int o = 0; o < 64; o++) sum = fmaf(wr[o], xr[o], sum);
        float v = sum * (g_out[oo] * rsqrtf(1.f + EPSV)) + b_out[oo];
        out[(b * 3 + oo) * NPTS + p0 + pt] = lrelu(v);
    }
}

// ---------------------------------------------------------------------------
extern "C" void kernel_launch(void* const* d_in, const int* in_sizes, int n_in,
                              void* d_out, int out_size) {
    const float* x     = (const float*)d_in[0];
    const float* w0    = (const float*)d_in[1];
    const float* g0    = (const float*)d_in[2];
    const float* b0    = (const float*)d_in[3];
    const float* w1    = (const float*)d_in[4];
    const float* g1    = (const float*)d_in[5];
    const float* b1    = (const float*)d_in[6];
    const float* w_out = (const float*)d_in[7];
    const float* g_out = (const float*)d_in[8];
    const float* b_out = (const float*)d_in[9];
    float* out = (float*)d_out;

    const int knn_smem  = NPTS * 16 + QPB * BCAP * 8 + 64;   // 82 KB
    const int main_smem = SM_FLOATS * 4;                     // 204288

    cudaFuncSetAttribute(knn_prep_kernel, cudaFuncAttributeMaxDynamicSharedMemorySize,
                         knn_smem);
    cudaFuncSetAttribute(main_mma, cudaFuncAttributeMaxDynamicSharedMemorySize,
                         main_smem);

    knn_prep_kernel<<<dim3(NPTS / QPB, BATCH), 512, knn_smem>>>(x, w0, g0, w1, g1);
    main_mma<<<dim3(NPTS / 16, BATCH), 640, main_smem>>>(x, b0, b1, w_out,
                                                         g_out, b_out, out);
}

// round 13
// speedup vs baseline: 2.1731x; 1.1601x over previous
#include <cuda_runtime.h>
#include <cuda_fp16.h>
#include <cstdint>

#define BATCH 4
#define NPTS  4096
#define KNB   20
#define EPSV  1e-5f
#define SLOPE 0.2f
#define QPB  16
#define BCAP 128

// main kernel smem layout (float offsets)
#define OF_WPS 0          // 96 rows * 132 u32 = 12672  (f16x2 B tiles)
#define OF_Z   12672      // 320 * 66  (z epilogue buffer)
#define OF_FT  33792      // 320 * 9
#define OF_X1  36672      // 16 * 64
#define OF_W0  37696      // 384
#define OF_B0  38080      // 64
#define OF_B1  38144      // 64
#define OF_WO  38208      // 192
#define SM_FLOATS 38400   // 153600 bytes

__device__ unsigned g_wb[96 * 128];   // f16x2: row R=k16*4+s, pos q*16+h*8+nt
__device__ float    g_w0f[384];
__device__ int      g_idx[BATCH * NPTS * KNB];

__device__ __forceinline__ float lrelu(float v) { return fmaxf(v, SLOPE * v); }

__device__ __forceinline__ unsigned fkey(float d) {
    unsigned b = __float_as_uint(d);
    return b ^ ((unsigned)((int)b >> 31) | 0x80000000u);
}
__device__ __forceinline__ uint32_t packh2(float lo, float hi) {
    uint32_t r;
    asm("cvt.rn.f16x2.f32 %0, %1, %2;" : "=r"(r) : "f"(hi), "f"(lo));
    return r;
}

#define MMA_F16(d, a0, a1, a2, a3, b0, b1) \
    asm volatile("mma.sync.aligned.m16n8k16.row.col.f32.f16.f16.f32 " \
        "{%0,%1,%2,%3}, {%4,%5,%6,%7}, {%8,%9}, {%0,%1,%2,%3};" \
        : "+f"((d)[0]), "+f"((d)[1]), "+f"((d)[2]), "+f"((d)[3]) \
        : "r"(a0), "r"(a1), "r"(a2), "r"(a3), "r"(b0), "r"(b1))

// ---------------------------------------------------------------------------
// KNN (threshold-filter, 16 q/block) + prep of f16x2 B tiles and w0 fold
// ---------------------------------------------------------------------------
__global__ void __launch_bounds__(512, 2) knn_prep_kernel(
    const float* __restrict__ x,
    const float* __restrict__ w0, const float* __restrict__ g0,
    const float* __restrict__ w1, const float* __restrict__ g1)
{
    extern __shared__ char dsm[];
    float4*             pts = reinterpret_cast<float4*>(dsm);
    unsigned long long* buf = reinterpret_cast<unsigned long long*>(dsm + 65536);
    unsigned*           cnt = reinterpret_cast<unsigned*>(dsm + 65536 + QPB * BCAP * 8);

    const int tid = threadIdx.x, lane = tid & 31, w = tid >> 5;
    const int b = blockIdx.y, q = blockIdx.x * QPB + w;
    const float* xb = x + b * 3 * NPTS;

    {   // prep distributed over 2048 blocks
        const int gt = (blockIdx.y * gridDim.x + blockIdx.x) * 512 + tid;
        const float inv = rsqrtf(1.f + EPSV);
        if (gt < 384) g_w0f[gt] = w0[gt] * g0[gt / 6] * inv;
        if (gt < 96 * 128) {
            int R = gt >> 7, p = gt & 127;
            int k16 = R >> 2, s = R & 3;
            int qq = p >> 4, h = (p >> 3) & 1, nt = p & 7;
            int kc = k16 * 16 + 2 * s + 8 * h;
            int n  = qq + 8 * nt;
            float sc = g1[n] * inv;
            int m0 = kc / 6,       c0 = kc - m0 * 6;
            int m1 = (kc + 1) / 6, c1 = (kc + 1) - m1 * 6;
            __half h0 = __float2half_rn(w1[(n * 6 + c0) * 64 + m0] * sc);
            __half h1 = __float2half_rn(w1[(n * 6 + c1) * 64 + m1] * sc);
            unsigned u0 = (unsigned)__half_as_ushort(h0);
            unsigned u1 = (unsigned)__half_as_ushort(h1);
            g_wb[gt] = u0 | (u1 << 16);
        }
    }

    for (int i = tid; i < NPTS; i += 512) {
        float vx = xb[i], vy = xb[NPTS + i], vz = xb[2 * NPTS + i];
        pts[i] = make_float4(vx, vy, vz, fmaf(vx, vx, fmaf(vy, vy, vz * vz)));
    }
    if (tid < QPB) cnt[tid] = 0;
    __syncthreads();

    const float4 qp = pts[q];
    const float qx = qp.x, qy = qp.y, qz = qp.z;
    const float INF = __int_as_float(0x7f800000);

    float mn[8];
#pragma unroll
    for (int u = 0; u < 8; u++) mn[u] = INF;
    for (int t = 0; t < NPTS / 32; t += 8) {
#pragma unroll
        for (int u = 0; u < 8; u++) {
            float4 p = pts[((t + u) << 5) + lane];
            mn[u] = fminf(mn[u],
                fmaf(-2.f, fmaf(qx, p.x, fmaf(qy, p.y, qz * p.z)), p.w));
        }
    }
    float val = fminf(fminf(fminf(mn[0], mn[1]), fminf(mn[2], mn[3])),
                      fminf(fminf(mn[4], mn[5]), fminf(mn[6], mn[7])));

    float T = INF;
    for (int r = 0; r < KNB; r++) {
        float wmin = val;
#pragma unroll
        for (int d = 16; d; d >>= 1)
            wmin = fminf(wmin, __shfl_xor_sync(0xffffffffu, wmin, d));
        unsigned msk = __ballot_sync(0xffffffffu, val == wmin);
        if (lane == (__ffs(msk) - 1)) val = INF;
        T = wmin;
    }

    unsigned long long* myb = buf + w * BCAP;
    for (int t = 0; t < NPTS / 32; t++) {
        const int j = (t << 5) + lane;
        float4 p = pts[j];
        float d = fmaf(-2.f, fmaf(qx, p.x, fmaf(qy, p.y, qz * p.z)), p.w);
        if (d <= T) {
            unsigned pos = atomicAdd(&cnt[w], 1u);
            if (pos < BCAP)
                myb[pos] = ((unsigned long long)fkey(d) << 32) | (unsigned)j;
        }
    }
    __syncwarp();
    const unsigned nb = cnt[w];

    int* obase = g_idx + (b * NPTS + q) * KNB;
    if (nb <= BCAP) {
        unsigned long long v[BCAP / 32];
#pragma unroll
        for (int u = 0; u < BCAP / 32; u++) {
            int t = lane + u * 32;
            v[u] = (t < (int)nb) ? myb[t] : 0xffffffffffffffffull;
        }
        for (int r = 0; r < KNB; r++) {
            unsigned long long lmin = v[0]; int lpos = 0;
#pragma unroll
            for (int u = 1; u < BCAP / 32; u++)
                if (v[u] < lmin) { lmin = v[u]; lpos = u; }
            unsigned long long wmin = lmin;
#pragma unroll
            for (int d = 16; d; d >>= 1) {
                unsigned long long o = __shfl_xor_sync(0xffffffffu, wmin, d);
                wmin = (o < wmin) ? o : wmin;
            }
            if (lmin == wmin) {
#pragma unroll
                for (int u = 0; u < BCAP / 32; u++)
                    if (u == lpos) v[u] = 0xffffffffffffffffull;
            }
            if (lane == 0) obase[r] = (int)(unsigned)(wmin & 0xffffffffull);
        }
    } else {
        unsigned long long last = 0;
        for (int r = 0; r < KNB; r++) {
            unsigned long long best = 0xffffffffffffffffull;
            for (int t = 0; t < NPTS / 32; t++) {
                const int j = (t << 5) + lane;
                float4 p = pts[j];
                float d = fmaf(-2.f, fmaf(qx, p.x, fmaf(qy, p.y, qz * p.z)), p.w);
                unsigned long long kk = ((unsigned long long)fkey(d) << 32) | (unsigned)j;
                if (kk > last && kk < best) best = kk;
            }
#pragma unroll
            for (int d = 16; d; d >>= 1) {
                unsigned long long o = __shfl_xor_sync(0xffffffffu, best, d);
                best = (o < best) ? o : best;
            }
            if (lane == 0) obase[r] = (int)(unsigned)(best & 0xffffffffull);
            last = best;
        }
    }
}

// ---------------------------------------------------------------------------
// Main: f16 mma.sync m16n8k16 GEMM, 640 thr / 20 warps, warp = 16-edge
// M-stripe. y register-distributed (shfl), B conflict-free LDS.128.
// ---------------------------------------------------------------------------
__global__ void __launch_bounds__(640, 1) main_mma(
    const float* __restrict__ x,     const float* __restrict__ b0,
    const float* __restrict__ b1,    const float* __restrict__ w_out,
    const float* __restrict__ g_out, const float* __restrict__ b_out,
    float* __restrict__ out)
{
    extern __shared__ float sm[];
    unsigned* wps = reinterpret_cast<unsigned*>(sm + OF_WPS);  // stride 132 u32
    float* zs  = sm + OF_Z;
    float* fts = sm + OF_FT;
    float* x1s = sm + OF_X1;
    float* w0f = sm + OF_W0;
    float* b0s = sm + OF_B0;
    float* b1s = sm + OF_B1;
    float* wos = sm + OF_WO;

    const int tid = threadIdx.x, lane = tid & 31, wid = tid >> 5;
    const int b = blockIdx.y, p0 = blockIdx.x * 16;
    const float* xb = x + b * 3 * NPTS;

    if (tid < 320) {
        int n = p0 + tid / 20;
        int jn = g_idx[(b * NPTS + n) * KNB + tid % 20];
        float xi0 = xb[n],  xi1 = xb[NPTS + n],  xi2 = xb[2 * NPTS + n];
        float xj0 = xb[jn], xj1 = xb[NPTS + jn], xj2 = xb[2 * NPTS + jn];
        float* fr = fts + tid * 9;
        fr[0] = xj0 - xi0; fr[1] = xj1 - xi1; fr[2] = xj2 - xi2;
        fr[3] = xi0; fr[4] = xi1; fr[5] = xi2;
    }
    // B tiles -> smem rows of stride 132 u32 (128 data + 4 pad)
    for (int g4 = tid; g4 < 3072; g4 += 640) {
        uint4 v = reinterpret_cast<const uint4*>(g_wb)[g4];
        int row = g4 >> 5, pos4 = g4 & 31;
        *reinterpret_cast<uint4*>(wps + row * 132 + pos4 * 4) = v;
    }
    if (tid < 384) w0f[tid] = g_w0f[tid];
    if (tid < 64) { b0s[tid] = b0[tid]; b1s[tid] = b1[tid]; }
    if (tid < 192) wos[tid] = w_out[tid];
    __syncthreads();

    const int s = lane & 3, q = lane >> 2;
    const int rA = wid * 16 + q;
    const int qb = q << 2;

    // register-distributed y: lane (s,q) holds y[rA][4k+s], y[rA+8][4k+s]
    float yr0[16], yr1[16];
    {
        const float* fA = fts + rA * 9;
        const float* fB = fts + (rA + 8) * 9;
        float a0 = fA[0], a1 = fA[1], a2 = fA[2], a3 = fA[3], a4 = fA[4], a5 = fA[5];
        float c0 = fB[0], c1 = fB[1], c2 = fB[2], c3 = fB[3], c4 = fB[4], c5 = fB[5];
#pragma unroll
        for (int k = 0; k < 16; k++) {
            int m = 4 * k + s;
            const float* wr = w0f + m * 6;
            float bb = b0s[m];
            float u = bb, v = bb;
            u = fmaf(wr[0], a0, u); v = fmaf(wr[0], c0, v);
            u = fmaf(wr[1], a1, u); v = fmaf(wr[1], c1, v);
            u = fmaf(wr[2], a2, u); v = fmaf(wr[2], c2, v);
            u = fmaf(wr[3], a3, u); v = fmaf(wr[3], c3, v);
            u = fmaf(wr[4], a4, u); v = fmaf(wr[4], c4, v);
            u = fmaf(wr[5], a5, u); v = fmaf(wr[5], c5, v);
            yr0[k] = lrelu(u);
            yr1[k] = lrelu(v);
        }
    }

    // lane-rotated ft cache: fcA[i] = ft[rA][(2s+i)%6]
    float fcA[6], fcB[6];
#pragma unroll
    for (int i = 0; i < 6; i++) {
        int c = (2 * s + i) % 6;
        fcA[i] = fts[rA * 9 + c];
        fcB[i] = fts[(rA + 8) * 9 + c];
    }

    float dA[8][4];
#pragma unroll
    for (int nt = 0; nt < 8; nt++)
#pragma unroll
        for (int u = 0; u < 4; u++) dA[nt][u] = 0.f;

#pragma unroll 1
    for (int k3 = 0; k3 < 8; k3++) {
#pragma unroll
        for (int t = 0; t < 3; t++) {
            const int k16 = k3 * 3 + t;
            const int K0 = k16 * 16 + 2 * s;               // per-lane
            const int r_lo = ((k16 * 16) / 6) >> 2;        // warp-uniform (proven)
            const int r_hi = ((k16 * 16 + 8) / 6) >> 2;    // warp-uniform (proven)
            const int i0 = (4 * t) % 6, i1 = (4 * t + 1) % 6;
            const int i2 = (4 * t + 2) % 6, i3 = (4 * t + 3) % 6;

            int m_l0 = K0 / 6, m_l1 = (K0 + 1) / 6;
            int m_h0 = (K0 + 8) / 6, m_h1 = (K0 + 9) / 6;

            float yA_l0 = __shfl_sync(0xffffffffu, yr0[r_lo], qb + (m_l0 & 3));
            float yA_l1 = __shfl_sync(0xffffffffu, yr0[r_lo], qb + (m_l1 & 3));
            float yA_h0 = __shfl_sync(0xffffffffu, yr0[r_hi], qb + (m_h0 & 3));
            float yA_h1 = __shfl_sync(0xffffffffu, yr0[r_hi], qb + (m_h1 & 3));
            float yB_l0 = __shfl_sync(0xffffffffu, yr1[r_lo], qb + (m_l0 & 3));
            float yB_l1 = __shfl_sync(0xffffffffu, yr1[r_lo], qb + (m_l1 & 3));
            float yB_h0 = __shfl_sync(0xffffffffu, yr1[r_hi], qb + (m_h0 & 3));
            float yB_h1 = __shfl_sync(0xffffffffu, yr1[r_hi], qb + (m_h1 & 3));

            uint32_t a0 = packh2(yA_l0 * fcA[i0], yA_l1 * fcA[i1]);
            uint32_t a1 = packh2(yB_l0 * fcB[i0], yB_l1 * fcB[i1]);
            uint32_t a2 = packh2(yA_h0 * fcA[i2], yA_h1 * fcA[i3]);
            uint32_t a3 = packh2(yB_h0 * fcB[i2], yB_h1 * fcB[i3]);

            const unsigned* wrow = wps + (k16 * 4 + s) * 132 + q * 16;
            uint4 B0a = *reinterpret_cast<const uint4*>(wrow);        // h0 nt0-3
            uint4 B0b = *reinterpret_cast<const uint4*>(wrow + 4);    // h0 nt4-7
            uint4 B1a = *reinterpret_cast<const uint4*>(wrow + 8);    // h1 nt0-3
            uint4 B1b = *reinterpret_cast<const uint4*>(wrow + 12);   // h1 nt4-7

            MMA_F16(dA[0], a0, a1, a2, a3, B0a.x, B1a.x);
            MMA_F16(dA[1], a0, a1, a2, a3, B0a.y, B1a.y);
            MMA_F16(dA[2], a0, a1, a2, a3, B0a.z, B1a.z);
            MMA_F16(dA[3], a0, a1, a2, a3, B0a.w, B1a.w);
            MMA_F16(dA[4], a0, a1, a2, a3, B0b.x, B1b.x);
            MMA_F16(dA[5], a0, a1, a2, a3, B0b.y, B1b.y);
            MMA_F16(dA[6], a0, a1, a2, a3, B0b.z, B1b.z);
            MMA_F16(dA[7], a0, a1, a2, a3, B0b.w, B1b.w);
        }
    }

    // z = lrelu(D + b1) -> zs rows (D col = nt*8 + s*2)
    __syncwarp();
#pragma unroll
    for (int nt = 0; nt < 8; nt++) {
        int c = nt * 8 + s * 2;
        float bc0 = b1s[c], bc1 = b1s[c + 1];
        *reinterpret_cast<float2*>(zs + rA * 66 + c) =
            make_float2(lrelu(dA[nt][0] + bc0), lrelu(dA[nt][1] + bc1));
        *reinterpret_cast<float2*>(zs + (rA + 8) * 66 + c) =
            make_float2(lrelu(dA[nt][2] + bc0), lrelu(dA[nt][3] + bc1));
    }
    __syncthreads();

    // max over k per (point, col)
    for (int it = tid; it < 16 * 64; it += 640) {
        int p = it >> 6, col = it & 63;
        const float* zr = zs + (p * 20) * 66 + col;
        float m = -3.4e38f;
#pragma unroll
        for (int kk = 0; kk < 20; kk++) m = fmaxf(m, zr[kk * 66]);
        x1s[it] = m;
    }
    __syncthreads();

    if (tid < 48) {
        int oo = tid >> 4, pt = tid & 15;
        const float* wr = wos + oo * 64;
        const float* xr = x1s + pt * 64;
        float sum = 0.f;
#pragma unroll
        for (int o = 0; o < 64; o++) sum = fmaf(wr[o], xr[o], sum);
        float v = sum * (g_out[oo] * rsqrtf(1.f + EPSV)) + b_out[oo];
        out[(b * 3 + oo) * NPTS + p0 + pt] = lrelu(v);
    }
}

// ---------------------------------------------------------------------------
extern "C" void kernel_launch(void* const* d_in, const int* in_sizes, int n_in,
                              void* d_out, int out_size) {
    const float* x     = (const float*)d_in[0];
    const float* w0    = (const float*)d_in[1];
    const float* g0    = (const float*)d_in[2];
    const float* b0    = (const float*)d_in[3];
    const float* w1    = (const float*)d_in[4];
    const float* g1    = (const float*)d_in[5];
    const float* b1    = (const float*)d_in[6];
    const float* w_out = (const float*)d_in[7];
    const float* g_out = (const float*)d_in[8];
    const float* b_out = (const float*)d_in[9];
    float* out = (float*)d_out;

    const int knn_smem  = NPTS * 16 + QPB * BCAP * 8 + 64;   // ~82 KB
    const int main_smem = SM_FLOATS * 4;                     // 153600

    cudaFuncSetAttribute(knn_prep_kernel, cudaFuncAttributeMaxDynamicSharedMemorySize,
                         knn_smem);
    cudaFuncSetAttribute(main_mma, cudaFuncAttributeMaxDynamicSharedMemorySize,
                         main_smem);

    knn_prep_kernel<<<dim3(NPTS / QPB, BATCH), 512, knn_smem>>>(x, w0, g0, w1, g1);
    main_mma<<<dim3(NPTS / 16, BATCH), 640, main_smem>>>(x, b0, b1, w_out,
                                                         g_out, b_out, out);
}

// round 14
// speedup vs baseline: 2.3652x; 1.0884x over previous
#include <cuda_runtime.h>
#include <cuda_fp16.h>
#include <cstdint>

#define BATCH 4
#define NPTS  4096
#define KNB   20
#define EPSV  1e-5f
#define SLOPE 0.2f
#define QPB  16
#define BCAP 128

// main kernel smem layout (float offsets)
#define OF_WPS 0          // 96 rows * 132 u32 = 12672  (f16x2 B tiles)
#define OF_Z   12672      // 320 * 66  (z epilogue buffer)
#define OF_FT  33792      // 320 * 9
#define OF_X1  36672      // 16 * 64
#define OF_W0  37696      // 384
#define OF_B0  38080      // 64
#define OF_B1  38144      // 64
#define OF_WO  38208      // 192
#define SM_FLOATS 38400   // 153600 bytes

__device__ unsigned g_wb[96 * 128];   // f16x2 B, K-permuted (see prep)
__device__ float    g_w0f[384];
__device__ int      g_idx[BATCH * NPTS * KNB];

__device__ __forceinline__ float lrelu(float v) { return fmaxf(v, SLOPE * v); }

__device__ __forceinline__ unsigned fkey(float d) {
    unsigned b = __float_as_uint(d);
    return b ^ ((unsigned)((int)b >> 31) | 0x80000000u);
}
__device__ __forceinline__ uint32_t packh2(float lo, float hi) {
    uint32_t r;
    asm("cvt.rn.f16x2.f32 %0, %1, %2;" : "=r"(r) : "f"(hi), "f"(lo));
    return r;
}

#define MMA_F16(d, a0, a1, a2, a3, b0, b1) \
    asm volatile("mma.sync.aligned.m16n8k16.row.col.f32.f16.f16.f32 " \
        "{%0,%1,%2,%3}, {%4,%5,%6,%7}, {%8,%9}, {%0,%1,%2,%3};" \
        : "+f"((d)[0]), "+f"((d)[1]), "+f"((d)[2]), "+f"((d)[3]) \
        : "r"(a0), "r"(a1), "r"(a2), "r"(a3), "r"(b0), "r"(b1))

// profiling parity shim: makes launches/invocation = 5 so ncu -s5 -c1 lands
// on the knn kernel next round (was always main at period 2)
__global__ void nop_kernel() {}

// ---------------------------------------------------------------------------
// KNN (threshold-filter, 16 q/block) + prep of K-PERMUTED f16x2 B tiles.
// K-permutation: slot p = 4*k16 + i of lane-class s carries (m, c) =
// (4*(p&15)+s, p>>4). This makes the main kernel's y-register and ft-channel
// indices compile-time (no shfl). Bijective per class: p in [0,96) <->
// (m ≡ s mod 4) x (c in [0,6)).
// ---------------------------------------------------------------------------
__global__ void __launch_bounds__(512, 2) knn_prep_kernel(
    const float* __restrict__ x,
    const float* __restrict__ w0, const float* __restrict__ g0,
    const float* __restrict__ w1, const float* __restrict__ g1)
{
    extern __shared__ char dsm[];
    float4*             pts = reinterpret_cast<float4*>(dsm);
    unsigned long long* buf = reinterpret_cast<unsigned long long*>(dsm + 65536);
    unsigned*           cnt = reinterpret_cast<unsigned*>(dsm + 65536 + QPB * BCAP * 8);

    const int tid = threadIdx.x, lane = tid & 31, w = tid >> 5;
    const int b = blockIdx.y, q = blockIdx.x * QPB + w;
    const float* xb = x + b * 3 * NPTS;

    {   // prep distributed over 2048 blocks
        const int gt = (blockIdx.y * gridDim.x + blockIdx.x) * 512 + tid;
        const float inv = rsqrtf(1.f + EPSV);
        if (gt < 384) g_w0f[gt] = w0[gt] * g0[gt / 6] * inv;
        if (gt < 96 * 128) {
            int R = gt >> 7, pos = gt & 127;
            int k16 = R >> 2, s = R & 3;
            int qq = pos >> 4, h = (pos >> 3) & 1, nt = pos & 7;
            int n  = qq + 8 * nt;
            float sc = g1[n] * inv;
            int p0 = 4 * k16 + 2 * h, p1 = p0 + 1;
            int m0 = 4 * (p0 & 15) + s, c0 = p0 >> 4;
            int m1 = 4 * (p1 & 15) + s, c1 = p1 >> 4;
            __half h0 = __float2half_rn(w1[(n * 6 + c0) * 64 + m0] * sc);
            __half h1 = __float2half_rn(w1[(n * 6 + c1) * 64 + m1] * sc);
            unsigned u0 = (unsigned)__half_as_ushort(h0);
            unsigned u1 = (unsigned)__half_as_ushort(h1);
            g_wb[gt] = u0 | (u1 << 16);
        }
    }

    for (int i = tid; i < NPTS; i += 512) {
        float vx = xb[i], vy = xb[NPTS + i], vz = xb[2 * NPTS + i];
        pts[i] = make_float4(vx, vy, vz, fmaf(vx, vx, fmaf(vy, vy, vz * vz)));
    }
    if (tid < QPB) cnt[tid] = 0;
    __syncthreads();

    const float4 qp = pts[q];
    const float qx = qp.x, qy = qp.y, qz = qp.z;
    const float INF = __int_as_float(0x7f800000);

    float mn[8];
#pragma unroll
    for (int u = 0; u < 8; u++) mn[u] = INF;
    for (int t = 0; t < NPTS / 32; t += 8) {
#pragma unroll
        for (int u = 0; u < 8; u++) {
            float4 p = pts[((t + u) << 5) + lane];
            mn[u] = fminf(mn[u],
                fmaf(-2.f, fmaf(qx, p.x, fmaf(qy, p.y, qz * p.z)), p.w));
        }
    }
    float val = fminf(fminf(fminf(mn[0], mn[1]), fminf(mn[2], mn[3])),
                      fminf(fminf(mn[4], mn[5]), fminf(mn[6], mn[7])));

    float T = INF;
    for (int r = 0; r < KNB; r++) {
        float wmin = val;
#pragma unroll
        for (int d = 16; d; d >>= 1)
            wmin = fminf(wmin, __shfl_xor_sync(0xffffffffu, wmin, d));
        unsigned msk = __ballot_sync(0xffffffffu, val == wmin);
        if (lane == (__ffs(msk) - 1)) val = INF;
        T = wmin;
    }

    unsigned long long* myb = buf + w * BCAP;
    for (int t = 0; t < NPTS / 32; t++) {
        const int j = (t << 5) + lane;
        float4 p = pts[j];
        float d = fmaf(-2.f, fmaf(qx, p.x, fmaf(qy, p.y, qz * p.z)), p.w);
        if (d <= T) {
            unsigned pos = atomicAdd(&cnt[w], 1u);
            if (pos < BCAP)
                myb[pos] = ((unsigned long long)fkey(d) << 32) | (unsigned)j;
        }
    }
    __syncwarp();
    const unsigned nb = cnt[w];

    int* obase = g_idx + (b * NPTS + q) * KNB;
    if (nb <= BCAP) {
        unsigned long long v[BCAP / 32];
#pragma unroll
        for (int u = 0; u < BCAP / 32; u++) {
            int t = lane + u * 32;
            v[u] = (t < (int)nb) ? myb[t] : 0xffffffffffffffffull;
        }
        for (int r = 0; r < KNB; r++) {
            unsigned long long lmin = v[0]; int lpos = 0;
#pragma unroll
            for (int u = 1; u < BCAP / 32; u++)
                if (v[u] < lmin) { lmin = v[u]; lpos = u; }
            unsigned long long wmin = lmin;
#pragma unroll
            for (int d = 16; d; d >>= 1) {
                unsigned long long o = __shfl_xor_sync(0xffffffffu, wmin, d);
                wmin = (o < wmin) ? o : wmin;
            }
            if (lmin == wmin) {
#pragma unroll
                for (int u = 0; u < BCAP / 32; u++)
                    if (u == lpos) v[u] = 0xffffffffffffffffull;
            }
            if (lane == 0) obase[r] = (int)(unsigned)(wmin & 0xffffffffull);
        }
    } else {
        unsigned long long last = 0;
        for (int r = 0; r < KNB; r++) {
            unsigned long long best = 0xffffffffffffffffull;
            for (int t = 0; t < NPTS / 32; t++) {
                const int j = (t << 5) + lane;
                float4 p = pts[j];
                float d = fmaf(-2.f, fmaf(qx, p.x, fmaf(qy, p.y, qz * p.z)), p.w);
                unsigned long long kk = ((unsigned long long)fkey(d) << 32) | (unsigned)j;
                if (kk > last && kk < best) best = kk;
            }
#pragma unroll
            for (int d = 16; d; d >>= 1) {
                unsigned long long o = __shfl_xor_sync(0xffffffffu, best, d);
                best = (o < best) ? o : best;
            }
            if (lane == 0) obase[r] = (int)(unsigned)(best & 0xffffffffull);
            last = best;
        }
    }
}

// ---------------------------------------------------------------------------
// Main: f16 mma.sync m16n8k16 GEMM with shfl-free A-operand build.
// Lane class s owns exactly the K-slots whose m ≡ s (mod 4); per step k16:
// y reg indices 4*(k16&3)+i and ft channel c = k16>>2 are compile-time.
// ---------------------------------------------------------------------------
__global__ void __launch_bounds__(640, 1) main_mma(
    const float* __restrict__ x,     const float* __restrict__ b0,
    const float* __restrict__ b1,    const float* __restrict__ w_out,
    const float* __restrict__ g_out, const float* __restrict__ b_out,
    float* __restrict__ out)
{
    extern __shared__ float sm[];
    unsigned* wps = reinterpret_cast<unsigned*>(sm + OF_WPS);  // stride 132 u32
    float* zs  = sm + OF_Z;
    float* fts = sm + OF_FT;
    float* x1s = sm + OF_X1;
    float* w0f = sm + OF_W0;
    float* b0s = sm + OF_B0;
    float* b1s = sm + OF_B1;
    float* wos = sm + OF_WO;

    const int tid = threadIdx.x, lane = tid & 31, wid = tid >> 5;
    const int b = blockIdx.y, p0 = blockIdx.x * 16;
    const float* xb = x + b * 3 * NPTS;

    if (tid < 320) {
        int n = p0 + tid / 20;
        int jn = g_idx[(b * NPTS + n) * KNB + tid % 20];
        float xi0 = xb[n],  xi1 = xb[NPTS + n],  xi2 = xb[2 * NPTS + n];
        float xj0 = xb[jn], xj1 = xb[NPTS + jn], xj2 = xb[2 * NPTS + jn];
        float* fr = fts + tid * 9;
        fr[0] = xj0 - xi0; fr[1] = xj1 - xi1; fr[2] = xj2 - xi2;
        fr[3] = xi0; fr[4] = xi1; fr[5] = xi2;
    }
    for (int g4 = tid; g4 < 3072; g4 += 640) {
        uint4 v = reinterpret_cast<const uint4*>(g_wb)[g4];
        int row = g4 >> 5, pos4 = g4 & 31;
        *reinterpret_cast<uint4*>(wps + row * 132 + pos4 * 4) = v;
    }
    if (tid < 384) w0f[tid] = g_w0f[tid];
    if (tid < 64) { b0s[tid] = b0[tid]; b1s[tid] = b1[tid]; }
    if (tid < 192) wos[tid] = w_out[tid];
    __syncthreads();

    const int s = lane & 3, q = lane >> 2;
    const int rA = wid * 16 + q;

    // y: lane (s,q) holds y[rA][4k+s] (yr0), y[rA+8][4k+s] (yr1)
    float yr0[16], yr1[16];
    {
        const float* fA = fts + rA * 9;
        const float* fB = fts + (rA + 8) * 9;
        float a0 = fA[0], a1 = fA[1], a2 = fA[2], a3 = fA[3], a4 = fA[4], a5 = fA[5];
        float c0 = fB[0], c1 = fB[1], c2 = fB[2], c3 = fB[3], c4 = fB[4], c5 = fB[5];
#pragma unroll
        for (int k = 0; k < 16; k++) {
            int m = 4 * k + s;
            const float* wr = w0f + m * 6;
            float bb = b0s[m];
            float u = bb, v = bb;
            u = fmaf(wr[0], a0, u); v = fmaf(wr[0], c0, v);
            u = fmaf(wr[1], a1, u); v = fmaf(wr[1], c1, v);
            u = fmaf(wr[2], a2, u); v = fmaf(wr[2], c2, v);
            u = fmaf(wr[3], a3, u); v = fmaf(wr[3], c3, v);
            u = fmaf(wr[4], a4, u); v = fmaf(wr[4], c4, v);
            u = fmaf(wr[5], a5, u); v = fmaf(wr[5], c5, v);
            yr0[k] = lrelu(u);
            yr1[k] = lrelu(v);
        }
    }

    // full ft caches for both rows (constant-indexed; c is compile-time)
    float ftA[6], ftB[6];
#pragma unroll
    for (int i = 0; i < 6; i++) {
        ftA[i] = fts[rA * 9 + i];
        ftB[i] = fts[(rA + 8) * 9 + i];
    }

    float dA[8][4];
#pragma unroll
    for (int nt = 0; nt < 8; nt++)
#pragma unroll
        for (int u = 0; u < 4; u++) dA[nt][u] = 0.f;

    const unsigned* wbase = wps + s * 132 + q * 16;

#pragma unroll
    for (int k16 = 0; k16 < 24; k16++) {
        const int c  = k16 >> 2;            // compile-time
        const int kb = 4 * (k16 & 3);       // compile-time
        const float fA = ftA[c], fB = ftB[c];

        uint32_t a0 = packh2(yr0[kb] * fA,     yr0[kb + 1] * fA);
        uint32_t a1 = packh2(yr1[kb] * fB,     yr1[kb + 1] * fB);
        uint32_t a2 = packh2(yr0[kb + 2] * fA, yr0[kb + 3] * fA);
        uint32_t a3 = packh2(yr1[kb + 2] * fB, yr1[kb + 3] * fB);

        const unsigned* wrow = wbase + k16 * 4 * 132;
        uint4 B0a = *reinterpret_cast<const uint4*>(wrow);
        uint4 B0b = *reinterpret_cast<const uint4*>(wrow + 4);
        uint4 B1a = *reinterpret_cast<const uint4*>(wrow + 8);
        uint4 B1b = *reinterpret_cast<const uint4*>(wrow + 12);

        MMA_F16(dA[0], a0, a1, a2, a3, B0a.x, B1a.x);
        MMA_F16(dA[1], a0, a1, a2, a3, B0a.y, B1a.y);
        MMA_F16(dA[2], a0, a1, a2, a3, B0a.z, B1a.z);
        MMA_F16(dA[3], a0, a1, a2, a3, B0a.w, B1a.w);
        MMA_F16(dA[4], a0, a1, a2, a3, B0b.x, B1b.x);
        MMA_F16(dA[5], a0, a1, a2, a3, B0b.y, B1b.y);
        MMA_F16(dA[6], a0, a1, a2, a3, B0b.z, B1b.z);
        MMA_F16(dA[7], a0, a1, a2, a3, B0b.w, B1b.w);
    }

    // z = lrelu(D + b1) -> zs rows (D col = nt*8 + s*2)
    __syncwarp();
#pragma unroll
    for (int nt = 0; nt < 8; nt++) {
        int c = nt * 8 + s * 2;
        float bc0 = b1s[c], bc1 = b1s[c + 1];
        *reinterpret_cast<float2*>(zs + rA * 66 + c) =
            make_float2(lrelu(dA[nt][0] + bc0), lrelu(dA[nt][1] + bc1));
        *reinterpret_cast<float2*>(zs + (rA + 8) * 66 + c) =
            make_float2(lrelu(dA[nt][2] + bc0), lrelu(dA[nt][3] + bc1));
    }
    __syncthreads();

    for (int it = tid; it < 16 * 64; it += 640) {
        int p = it >> 6, col = it & 63;
        const float* zr = zs + (p * 20) * 66 + col;
        float m = -3.4e38f;
#pragma unroll
        for (int kk = 0; kk < 20; kk++) m = fmaxf(m, zr[kk * 66]);
        x1s[it] = m;
    }
    __syncthreads();

    if (tid < 48) {
        int oo = tid >> 4, pt = tid & 15;
        const float* wr = wos + oo * 64;
        const float* xr = x1s + pt * 64;
        float sum = 0.f;
#pragma unroll
        for (int o = 0; o < 64; o++) sum = fmaf(wr[o], xr[o], sum);
        float v = sum * (g_out[oo] * rsqrtf(1.f + EPSV)) + b_out[oo];
        out[(b * 3 + oo) * NPTS + p0 + pt] = lrelu(v);
    }
}

// ---------------------------------------------------------------------------
extern "C" void kernel_launch(void* const* d_in, const int* in_sizes, int n_in,
                              void* d_out, int out_size) {
    const float* x     = (const float*)d_in[0];
    const float* w0    = (const float*)d_in[1];
    const float* g0    = (const float*)d_in[2];
    const float* b0    = (const float*)d_in[3];
    const float* w1    = (const float*)d_in[4];
    const float* g1    = (const float*)d_in[5];
    const float* b1    = (const float*)d_in[6];
    const float* w_out = (const float*)d_in[7];
    const float* g_out = (const float*)d_in[8];
    const float* b_out = (const float*)d_in[9];
    float* out = (float*)d_out;

    const int knn_smem  = NPTS * 16 + QPB * BCAP * 8 + 64;   // ~82 KB
    const int main_smem = SM_FLOATS * 4;                     // 153600

    cudaFuncSetAttribute(knn_prep_kernel, cudaFuncAttributeMaxDynamicSharedMemorySize,
                         knn_smem);
    cudaFuncSetAttribute(main_mma, cudaFuncAttributeMaxDynamicSharedMemorySize,
                         main_smem);

    knn_prep_kernel<<<dim3(NPTS / QPB, BATCH), 512, knn_smem>>>(x, w0, g0, w1, g1);
    main_mma<<<dim3(NPTS / 16, BATCH), 640, main_smem>>>(x, b0, b1, w_out,
                                                         g_out, b_out, out);
    // parity shim: 5 launches/invocation so ncu (-s 5 -c 1) captures knn next
    nop_kernel<<<1, 1>>>();
    nop_kernel<<<1, 1>>>();
    nop_kernel<<<1, 1>>>();
}

// round 15
// speedup vs baseline: 2.4043x; 1.0166x over previous
#include <cuda_runtime.h>
#include <cuda_fp16.h>
#include <cstdint>

#define BATCH 4
#define NPTS  4096
#define KNB   20
#define EPSV  1e-5f
#define SLOPE 0.2f
#define BCAP 128

// knn smem layout (bytes)
#define KS_LM   0          // 16*512 floats = 32768
#define KS_BUF  32768      // 16*128 u64    = 16384
#define KS_QC   49152      // 16*3 floats (+pad) = 256
#define KS_TSH  49408      // 16 floats + pad    = 64
#define KS_CNT  49472      // 16 u32             = 64
#define KS_TOT  49536

// main kernel smem layout (float offsets)
#define OF_WPS 0          // 96 rows * 132 u32 = 12672  (f16x2 B tiles)
#define OF_Z   12672      // 320 * 66  (z epilogue buffer)
#define OF_FT  33792      // 320 * 9
#define OF_X1  36672      // 16 * 64
#define OF_W0  37696      // 384
#define OF_B0  38080      // 64
#define OF_B1  38144      // 64
#define OF_WO  38208      // 192
#define SM_FLOATS 38400   // 153600 bytes

__device__ unsigned g_wb[96 * 128];   // f16x2 B, K-permuted (see prep)
__device__ float    g_w0f[384];
__device__ int      g_idx[BATCH * NPTS * KNB];

__device__ __forceinline__ float lrelu(float v) { return fmaxf(v, SLOPE * v); }

__device__ __forceinline__ unsigned fkey(float d) {
    unsigned b = __float_as_uint(d);
    return b ^ ((unsigned)((int)b >> 31) | 0x80000000u);
}
__device__ __forceinline__ uint32_t packh2(float lo, float hi) {
    uint32_t r;
    asm("cvt.rn.f16x2.f32 %0, %1, %2;" : "=r"(r) : "f"(hi), "f"(lo));
    return r;
}

#define MMA_F16(d, a0, a1, a2, a3, b0, b1) \
    asm volatile("mma.sync.aligned.m16n8k16.row.col.f32.f16.f16.f32 " \
        "{%0,%1,%2,%3}, {%4,%5,%6,%7}, {%8,%9}, {%0,%1,%2,%3};" \
        : "+f"((d)[0]), "+f"((d)[1]), "+f"((d)[2]), "+f"((d)[3]) \
        : "r"(a0), "r"(a1), "r"(a2), "r"(a3), "r"(b0), "r"(b1))

// ---------------------------------------------------------------------------
// KNN: register-tiled (each point loaded ONCE per block) + weight prep.
// Grid (NPTS/16, BATCH) = (256, 4), 512 threads (16 warps), 2 blocks/SM.
// Block handles 16 queries; warp w holds points [w*256, w*256+256) in regs.
// Pass 1: per query, per-lane min over its 8 disjoint points -> lm[q][512].
// Threshold: warp q extracts the 20th smallest of the 512 part-mins (with
// multiplicity). 512 disjoint parts => >=20 distinct points have d <= T and
// the global 20th smallest <= T, so the filter d <= T is exact.
// Pass 2: same registers, rare atomic append of (fkey(d)<<32|idx).
// Phase 3: per-warp exact top-20 via 20 warp-min rounds (ties -> lowest idx,
// matching top_k). Output order irrelevant downstream (max over k).
// ---------------------------------------------------------------------------
__global__ void __launch_bounds__(512, 2) knn_prep_kernel(
    const float* __restrict__ x,
    const float* __restrict__ w0, const float* __restrict__ g0,
    const float* __restrict__ w1, const float* __restrict__ g1)
{
    extern __shared__ char dsm[];
    float*              lm  = reinterpret_cast<float*>(dsm + KS_LM);
    unsigned long long* buf = reinterpret_cast<unsigned long long*>(dsm + KS_BUF);
    float*              qc  = reinterpret_cast<float*>(dsm + KS_QC);
    float*              Tsh = reinterpret_cast<float*>(dsm + KS_TSH);
    unsigned*           cnt = reinterpret_cast<unsigned*>(dsm + KS_CNT);

    const int tid = threadIdx.x, lane = tid & 31, w = tid >> 5;
    const int b = blockIdx.y, q0 = blockIdx.x * 16;
    const float* xb = x + b * 3 * NPTS;
    const float INF = __int_as_float(0x7f800000);

    {   // prep distributed over 1024 blocks (f16x2 B, K-permuted)
        const int gt = (blockIdx.y * gridDim.x + blockIdx.x) * 512 + tid;
        const float inv = rsqrtf(1.f + EPSV);
        if (gt < 384) g_w0f[gt] = w0[gt] * g0[gt / 6] * inv;
        if (gt < 96 * 128) {
            int R = gt >> 7, pos = gt & 127;
            int k16 = R >> 2, s = R & 3;
            int qq = pos >> 4, h = (pos >> 3) & 1, nt = pos & 7;
            int n  = qq + 8 * nt;
            float sc = g1[n] * inv;
            int p0 = 4 * k16 + 2 * h, p1 = p0 + 1;
            int m0 = 4 * (p0 & 15) + s, c0 = p0 >> 4;
            int m1 = 4 * (p1 & 15) + s, c1 = p1 >> 4;
            __half h0 = __float2half_rn(w1[(n * 6 + c0) * 64 + m0] * sc);
            __half h1 = __float2half_rn(w1[(n * 6 + c1) * 64 + m1] * sc);
            g_wb[gt] = (unsigned)__half_as_ushort(h0)
                     | ((unsigned)__half_as_ushort(h1) << 16);
        }
    }

    if (tid < 16) {
        qc[tid * 3 + 0] = xb[q0 + tid];
        qc[tid * 3 + 1] = xb[NPTS + q0 + tid];
        qc[tid * 3 + 2] = xb[2 * NPTS + q0 + tid];
        cnt[tid] = 0;
    }
    __syncthreads();

    // ---- load this warp's 256 points into registers (once) ----
    float4 P[8];
#pragma unroll
    for (int t = 0; t < 8; t++) {
        int j = w * 256 + t * 32 + lane;
        float px = xb[j], py = xb[NPTS + j], pz = xb[2 * NPTS + j];
        P[t] = make_float4(px, py, pz, fmaf(px, px, fmaf(py, py, pz * pz)));
    }

    // ---- pass 1: per-query lane mins ----
#pragma unroll 1
    for (int q = 0; q < 16; q++) {
        float qx = qc[q * 3], qy = qc[q * 3 + 1], qz = qc[q * 3 + 2];
        float mnv = INF;
#pragma unroll
        for (int t = 0; t < 8; t++) {
            float d = fmaf(-2.f, fmaf(qx, P[t].x, fmaf(qy, P[t].y, qz * P[t].z)),
                           P[t].w);
            mnv = fminf(mnv, d);
        }
        lm[q * 512 + w * 32 + lane] = mnv;
    }
    __syncthreads();

    // ---- threshold: warp w handles query w ----
    {
        float v[16];
#pragma unroll
        for (int u = 0; u < 16; u++) v[u] = lm[w * 512 + lane + u * 32];
        float T = INF;
        for (int r = 0; r < KNB; r++) {
            float lmin = v[0]; int lpos = 0;
#pragma unroll
            for (int u = 1; u < 16; u++)
                if (v[u] < lmin) { lmin = v[u]; lpos = u; }
            float wmin = lmin;
#pragma unroll
            for (int d = 16; d; d >>= 1)
                wmin = fminf(wmin, __shfl_xor_sync(0xffffffffu, wmin, d));
            unsigned msk = __ballot_sync(0xffffffffu, lmin == wmin);
            if (lane == (__ffs(msk) - 1)) {
#pragma unroll
                for (int u = 0; u < 16; u++)
                    if (u == lpos) v[u] = INF;
            }
            T = wmin;
        }
        if (lane == 0) Tsh[w] = T;
    }
    __syncthreads();

    // ---- pass 2: compact passers from registers ----
#pragma unroll 1
    for (int q = 0; q < 16; q++) {
        float T = Tsh[q];
        float qx = qc[q * 3], qy = qc[q * 3 + 1], qz = qc[q * 3 + 2];
#pragma unroll
        for (int t = 0; t < 8; t++) {
            float d = fmaf(-2.f, fmaf(qx, P[t].x, fmaf(qy, P[t].y, qz * P[t].z)),
                           P[t].w);
            if (d <= T) {
                unsigned pos = atomicAdd(&cnt[q], 1u);
                if (pos < BCAP) {
                    int j = w * 256 + t * 32 + lane;
                    buf[q * BCAP + pos] =
                        ((unsigned long long)fkey(d) << 32) | (unsigned)j;
                }
            }
        }
    }
    __syncthreads();

    // ---- phase 3: warp w -> exact top-20 of query w ----
    {
        const unsigned nb = cnt[w];
        int* obase = g_idx + (b * NPTS + q0 + w) * KNB;
        if (nb <= BCAP) {
            unsigned long long v[BCAP / 32];
#pragma unroll
            for (int u = 0; u < BCAP / 32; u++) {
                int t = lane + u * 32;
                v[u] = (t < (int)nb) ? buf[w * BCAP + t] : 0xffffffffffffffffull;
            }
            for (int r = 0; r < KNB; r++) {
                unsigned long long lmin = v[0]; int lpos = 0;
#pragma unroll
                for (int u = 1; u < BCAP / 32; u++)
                    if (v[u] < lmin) { lmin = v[u]; lpos = u; }
                unsigned long long wmin = lmin;
#pragma unroll
                for (int d = 16; d; d >>= 1) {
                    unsigned long long o = __shfl_xor_sync(0xffffffffu, wmin, d);
                    wmin = (o < wmin) ? o : wmin;
                }
                if (lmin == wmin) {
#pragma unroll
                    for (int u = 0; u < BCAP / 32; u++)
                        if (u == lpos) v[u] = 0xffffffffffffffffull;
                }
                if (lane == 0) obase[r] = (int)(unsigned)(wmin & 0xffffffffull);
            }
        } else {
            // pathological fallback: exact repeated warp-min over all points
            float qx = qc[w * 3], qy = qc[w * 3 + 1], qz = qc[w * 3 + 2];
            unsigned long long last = 0;
            for (int r = 0; r < KNB; r++) {
                unsigned long long best = 0xffffffffffffffffull;
                for (int t = 0; t < NPTS / 32; t++) {
                    int j = t * 32 + lane;
                    float px = xb[j], py = xb[NPTS + j], pz = xb[2 * NPTS + j];
                    float pp = fmaf(px, px, fmaf(py, py, pz * pz));
                    float d = fmaf(-2.f, fmaf(qx, px, fmaf(qy, py, qz * pz)), pp);
                    unsigned long long kk =
                        ((unsigned long long)fkey(d) << 32) | (unsigned)j;
                    if (kk > last && kk < best) best = kk;
                }
#pragma unroll
                for (int d = 16; d; d >>= 1) {
                    unsigned long long o = __shfl_xor_sync(0xffffffffu, best, d);
                    best = (o < best) ? o : best;
                }
                if (lane == 0) obase[r] = (int)(unsigned)(best & 0xffffffffull);
                last = best;
            }
        }
    }
}

// ---------------------------------------------------------------------------
// Main: f16 mma.sync m16n8k16 GEMM with shfl-free A-operand build (round 14).
// ---------------------------------------------------------------------------
__global__ void __launch_bounds__(640, 1) main_mma(
    const float* __restrict__ x,     const float* __restrict__ b0,
    const float* __restrict__ b1,    const float* __restrict__ w_out,
    const float* __restrict__ g_out, const float* __restrict__ b_out,
    float* __restrict__ out)
{
    extern __shared__ float sm[];
    unsigned* wps = reinterpret_cast<unsigned*>(sm + OF_WPS);  // stride 132 u32
    float* zs  = sm + OF_Z;
    float* fts = sm + OF_FT;
    float* x1s = sm + OF_X1;
    float* w0f = sm + OF_W0;
    float* b0s = sm + OF_B0;
    float* b1s = sm + OF_B1;
    float* wos = sm + OF_WO;

    const int tid = threadIdx.x, lane = tid & 31, wid = tid >> 5;
    const int b = blockIdx.y, p0 = blockIdx.x * 16;
    const float* xb = x + b * 3 * NPTS;

    if (tid < 320) {
        int n = p0 + tid / 20;
        int jn = g_idx[(b * NPTS + n) * KNB + tid % 20];
        float xi0 = xb[n],  xi1 = xb[NPTS + n],  xi2 = xb[2 * NPTS + n];
        float xj0 = xb[jn], xj1 = xb[NPTS + jn], xj2 = xb[2 * NPTS + jn];
        float* fr = fts + tid * 9;
        fr[0] = xj0 - xi0; fr[1] = xj1 - xi1; fr[2] = xj2 - xi2;
        fr[3] = xi0; fr[4] = xi1; fr[5] = xi2;
    }
    for (int g4 = tid; g4 < 3072; g4 += 640) {
        uint4 v = reinterpret_cast<const uint4*>(g_wb)[g4];
        int row = g4 >> 5, pos4 = g4 & 31;
        *reinterpret_cast<uint4*>(wps + row * 132 + pos4 * 4) = v;
    }
    if (tid < 384) w0f[tid] = g_w0f[tid];
    if (tid < 64) { b0s[tid] = b0[tid]; b1s[tid] = b1[tid]; }
    if (tid < 192) wos[tid] = w_out[tid];
    __syncthreads();

    const int s = lane & 3, q = lane >> 2;
    const int rA = wid * 16 + q;

    float yr0[16], yr1[16];
    {
        const float* fA = fts + rA * 9;
        const float* fB = fts + (rA + 8) * 9;
        float a0 = fA[0], a1 = fA[1], a2 = fA[2], a3 = fA[3], a4 = fA[4], a5 = fA[5];
        float c0 = fB[0], c1 = fB[1], c2 = fB[2], c3 = fB[3], c4 = fB[4], c5 = fB[5];
#pragma unroll
        for (int k = 0; k < 16; k++) {
            int m = 4 * k + s;
            const float* wr = w0f + m * 6;
            float bb = b0s[m];
            float u = bb, v = bb;
            u = fmaf(wr[0], a0, u); v = fmaf(wr[0], c0, v);
            u = fmaf(wr[1], a1, u); v = fmaf(wr[1], c1, v);
            u = fmaf(wr[2], a2, u); v = fmaf(wr[2], c2, v);
            u = fmaf(wr[3], a3, u); v = fmaf(wr[3], c3, v);
            u = fmaf(wr[4], a4, u); v = fmaf(wr[4], c4, v);
            u = fmaf(wr[5], a5, u); v = fmaf(wr[5], c5, v);
            yr0[k] = lrelu(u);
            yr1[k] = lrelu(v);
        }
    }

    float ftA[6], ftB[6];
#pragma unroll
    for (int i = 0; i < 6; i++) {
        ftA[i] = fts[rA * 9 + i];
        ftB[i] = fts[(rA + 8) * 9 + i];
    }

    float dA[8][4];
#pragma unroll
    for (int nt = 0; nt < 8; nt++)
#pragma unroll
        for (int u = 0; u < 4; u++) dA[nt][u] = 0.f;

    const unsigned* wbase = wps + s * 132 + q * 16;

#pragma unroll
    for (int k16 = 0; k16 < 24; k16++) {
        const int c  = k16 >> 2;
        const int kb = 4 * (k16 & 3);
        const float fA = ftA[c], fB = ftB[c];

        uint32_t a0 = packh2(yr0[kb] * fA,     yr0[kb + 1] * fA);
        uint32_t a1 = packh2(yr1[kb] * fB,     yr1[kb + 1] * fB);
        uint32_t a2 = packh2(yr0[kb + 2] * fA, yr0[kb + 3] * fA);
        uint32_t a3 = packh2(yr1[kb + 2] * fB, yr1[kb + 3] * fB);

        const unsigned* wrow = wbase + k16 * 4 * 132;
        uint4 B0a = *reinterpret_cast<const uint4*>(wrow);
        uint4 B0b = *reinterpret_cast<const uint4*>(wrow + 4);
        uint4 B1a = *reinterpret_cast<const uint4*>(wrow + 8);
        uint4 B1b = *reinterpret_cast<const uint4*>(wrow + 12);

        MMA_F16(dA[0], a0, a1, a2, a3, B0a.x, B1a.x);
        MMA_F16(dA[1], a0, a1, a2, a3, B0a.y, B1a.y);
        MMA_F16(dA[2], a0, a1, a2, a3, B0a.z, B1a.z);
        MMA_F16(dA[3], a0, a1, a2, a3, B0a.w, B1a.w);
        MMA_F16(dA[4], a0, a1, a2, a3, B0b.x, B1b.x);
        MMA_F16(dA[5], a0, a1, a2, a3, B0b.y, B1b.y);
        MMA_F16(dA[6], a0, a1, a2, a3, B0b.z, B1b.z);
        MMA_F16(dA[7], a0, a1, a2, a3, B0b.w, B1b.w);
    }

    __syncwarp();
#pragma unroll
    for (int nt = 0; nt < 8; nt++) {
        int c = nt * 8 + s * 2;
        float bc0 = b1s[c], bc1 = b1s[c + 1];
        *reinterpret_cast<float2*>(zs + rA * 66 + c) =
            make_float2(lrelu(dA[nt][0] + bc0), lrelu(dA[nt][1] + bc1));
        *reinterpret_cast<float2*>(zs + (rA + 8) * 66 + c) =
            make_float2(lrelu(dA[nt][2] + bc0), lrelu(dA[nt][3] + bc1));
    }
    __syncthreads();

    for (int it = tid; it < 16 * 64; it += 640) {
        int p = it >> 6, col = it & 63;
        const float* zr = zs + (p * 20) * 66 + col;
        float m = -3.4e38f;
#pragma unroll
        for (int kk = 0; kk < 20; kk++) m = fmaxf(m, zr[kk * 66]);
        x1s[it] = m;
    }
    __syncthreads();

    if (tid < 48) {
        int oo = tid >> 4, pt = tid & 15;
        const float* wr = wos + oo * 64;
        const float* xr = x1s + pt * 64;
        float sum = 0.f;
#pragma unroll
        for (int o = 0; o < 64; o++) sum = fmaf(wr[o], xr[o], sum);
        float v = sum * (g_out[oo] * rsqrtf(1.f + EPSV)) + b_out[oo];
        out[(b * 3 + oo) * NPTS + p0 + pt] = lrelu(v);
    }
}

// ---------------------------------------------------------------------------
extern "C" void kernel_launch(void* const* d_in, const int* in_sizes, int n_in,
                              void* d_out, int out_size) {
    const float* x     = (const float*)d_in[0];
    const float* w0    = (const float*)d_in[1];
    const float* g0    = (const float*)d_in[2];
    const float* b0    = (const float*)d_in[3];
    const float* w1    = (const float*)d_in[4];
    const float* g1    = (const float*)d_in[5];
    const float* b1    = (const float*)d_in[6];
    const float* w_out = (const float*)d_in[7];
    const float* g_out = (const float*)d_in[8];
    const float* b_out = (const float*)d_in[9];
    float* out = (float*)d_out;

    const int main_smem = SM_FLOATS * 4;                     // 153600

    cudaFuncSetAttribute(knn_prep_kernel, cudaFuncAttributeMaxDynamicSharedMemorySize,
                         KS_TOT);
    cudaFuncSetAttribute(main_mma, cudaFuncAttributeMaxDynamicSharedMemorySize,
                         main_smem);

    knn_prep_kernel<<<dim3(NPTS / 16, BATCH), 512, KS_TOT>>>(x, w0, g0, w1, g1);
    main_mma<<<dim3(NPTS / 16, BATCH), 640, main_smem>>>(x, b0, b1, w_out,
                                                         g_out, b_out, out);
}